// round 1
// baseline (speedup 1.0000x reference)
#include <cuda_runtime.h>
#include <math.h>

#define Bz 2
#define Dd 1024
#define Ll 2048
#define Hh 16
#define DKk 64
#define Ee 1024   // H*DK

// Intermediates (no cudaMalloc allowed)
__device__ float g_Q[(size_t)Bz * Hh * Ll * DKk];
__device__ float g_K[(size_t)Bz * Hh * Ll * DKk];
__device__ float g_V[(size_t)Bz * Hh * Ll * DKk];
__device__ float g_Hd[(size_t)Bz * Ll * Ee];

// ---------------------------------------------------------------------------
// Kernel 1: fused QKV projection.
// q[b,h,l,k] = sum_d x[b,d,l] * Wq[h,d,k]   (Q pre-scaled by 1/sqrt(DK))
// Block: 256 threads, computes 64(L) x 64(DK) tile for one (b,h).
// ---------------------------------------------------------------------------
__global__ __launch_bounds__(256) void qkv_kernel(
    const float* __restrict__ x,
    const float* __restrict__ Wq,
    const float* __restrict__ Wk,
    const float* __restrict__ Wv)
{
    __shared__ float xs[16][64], wqs[16][64], wks[16][64], wvs[16][64];
    int bh = blockIdx.y;
    int b = bh >> 4, h = bh & 15;
    int l0 = blockIdx.x * 64;
    int t = threadIdx.x, ty = t >> 4, tx = t & 15;

    float aq[4][4] = {}, ak[4][4] = {}, av[4][4] = {};

    int kc = t >> 4;            // 0..15 (d within chunk)
    int c4 = (t & 15) * 4;      // 0..60

    const float* xp  = x  + ((size_t)b * Dd) * Ll + l0 + c4;
    const float* wqp = Wq + ((size_t)h * Dd) * DKk + c4;
    const float* wkp = Wk + ((size_t)h * Dd) * DKk + c4;
    const float* wvp = Wv + ((size_t)h * Dd) * DKk + c4;

    for (int d0 = 0; d0 < Dd; d0 += 16) {
        *(float4*)&xs[kc][c4]  = *(const float4*)&xp[(size_t)(d0 + kc) * Ll];
        *(float4*)&wqs[kc][c4] = *(const float4*)&wqp[(d0 + kc) * DKk];
        *(float4*)&wks[kc][c4] = *(const float4*)&wkp[(d0 + kc) * DKk];
        *(float4*)&wvs[kc][c4] = *(const float4*)&wvp[(d0 + kc) * DKk];
        __syncthreads();
        #pragma unroll
        for (int c = 0; c < 16; c++) {
            float a[4];
            #pragma unroll
            for (int i = 0; i < 4; i++) a[i] = xs[c][ty * 4 + i];
            float4 fq = *(float4*)&wqs[c][tx * 4];
            float4 fk = *(float4*)&wks[c][tx * 4];
            float4 fv = *(float4*)&wvs[c][tx * 4];
            float bq[4] = {fq.x, fq.y, fq.z, fq.w};
            float bk[4] = {fk.x, fk.y, fk.z, fk.w};
            float bv[4] = {fv.x, fv.y, fv.z, fv.w};
            #pragma unroll
            for (int i = 0; i < 4; i++) {
                #pragma unroll
                for (int j = 0; j < 4; j++) {
                    aq[i][j] += a[i] * bq[j];
                    ak[i][j] += a[i] * bk[j];
                    av[i][j] += a[i] * bv[j];
                }
            }
        }
        __syncthreads();
    }

    size_t obase = ((size_t)bh * Ll + l0 + ty * 4) * DKk + tx * 4;
    #pragma unroll
    for (int i = 0; i < 4; i++) {
        float4 q4 = make_float4(aq[i][0] * 0.125f, aq[i][1] * 0.125f,
                                aq[i][2] * 0.125f, aq[i][3] * 0.125f);
        float4 k4 = make_float4(ak[i][0], ak[i][1], ak[i][2], ak[i][3]);
        float4 v4 = make_float4(av[i][0], av[i][1], av[i][2], av[i][3]);
        *(float4*)&g_Q[obase + (size_t)i * DKk] = q4;
        *(float4*)&g_K[obase + (size_t)i * DKk] = k4;
        *(float4*)&g_V[obase + (size_t)i * DKk] = v4;
    }
}

// ---------------------------------------------------------------------------
// Kernel 2: flash attention per (b,h). Br = Bc = 64, online softmax.
// Key mask -> -1e30 score; query mask applied in epilogue.
// Dynamic smem: Qs[64][64], Kt/St[64][68] (shared), Vs[64][64], 4x[64] aux.
// ---------------------------------------------------------------------------
extern __shared__ float sm_f[];

__global__ __launch_bounds__(256) void flash_kernel(const float* __restrict__ mask)
{
    float* Qs   = sm_f;                       // 4096 floats [row][k]
    float* KtSt = sm_f + 4096;                // 4352 floats [64][68]
    float* Vs   = sm_f + 4096 + 4352;         // 4096 floats [row][k]
    float* mrow = Vs + 4096;                  // 64
    float* lrow = mrow + 64;                  // 64
    float* arow = lrow + 64;                  // 64
    float* kmsk = arow + 64;                  // 64

    int bh = blockIdx.y;
    int b = bh >> 4, h = bh & 15;
    int l0 = blockIdx.x * 64;
    int t = threadIdx.x, ty = t >> 4, tx = t & 15;

    const size_t qbase = ((size_t)bh * Ll + l0) * DKk;
    #pragma unroll
    for (int i = 0; i < 4; i++) {
        int fidx = t + i * 256;
        int r = fidx >> 4, k4 = (fidx & 15) * 4;
        *(float4*)&Qs[r * 64 + k4] = *(const float4*)&g_Q[qbase + (size_t)r * DKk + k4];
    }
    if (t < 64) { mrow[t] = -INFINITY; lrow[t] = 0.f; }

    float O[4][4] = {};

    for (int kb = 0; kb < Ll; kb += 64) {
        const size_t kbase = ((size_t)bh * Ll + kb) * DKk;
        #pragma unroll
        for (int i = 0; i < 4; i++) {
            int fidx = t + i * 256;
            int r = fidx >> 4, k4 = (fidx & 15) * 4;
            float4 kv = *(const float4*)&g_K[kbase + (size_t)r * DKk + k4];
            KtSt[(k4 + 0) * 68 + r] = kv.x;
            KtSt[(k4 + 1) * 68 + r] = kv.y;
            KtSt[(k4 + 2) * 68 + r] = kv.z;
            KtSt[(k4 + 3) * 68 + r] = kv.w;
            *(float4*)&Vs[r * 64 + k4] = *(const float4*)&g_V[kbase + (size_t)r * DKk + k4];
        }
        if (t < 64) kmsk[t] = mask[(size_t)b * Ll + kb + t];
        __syncthreads();

        // S = Q * K^T  (scale already folded into Q)
        float s[4][4] = {};
        #pragma unroll 4
        for (int c = 0; c < 64; c++) {
            float a[4];
            #pragma unroll
            for (int i = 0; i < 4; i++) a[i] = Qs[(ty * 4 + i) * 64 + c];
            float4 kf = *(float4*)&KtSt[c * 68 + tx * 4];
            float bb[4] = {kf.x, kf.y, kf.z, kf.w};
            #pragma unroll
            for (int i = 0; i < 4; i++)
                #pragma unroll
                for (int j = 0; j < 4; j++)
                    s[i][j] += a[i] * bb[j];
        }
        __syncthreads();   // Kt no longer needed; reuse as St

        // masked scores -> St
        float km[4] = {kmsk[tx * 4 + 0], kmsk[tx * 4 + 1],
                       kmsk[tx * 4 + 2], kmsk[tx * 4 + 3]};
        #pragma unroll
        for (int i = 0; i < 4; i++) {
            float4 sv;
            sv.x = (km[0] > 0.5f) ? s[i][0] : -1e30f;
            sv.y = (km[1] > 0.5f) ? s[i][1] : -1e30f;
            sv.z = (km[2] > 0.5f) ? s[i][2] : -1e30f;
            sv.w = (km[3] > 0.5f) ? s[i][3] : -1e30f;
            *(float4*)&KtSt[(ty * 4 + i) * 68 + tx * 4] = sv;
        }
        __syncthreads();

        // online softmax: 4 lanes per row
        {
            int r = t >> 2, q = t & 3;
            float* Srow = &KtSt[r * 68 + q * 16];
            float pm = -INFINITY;
            #pragma unroll
            for (int c = 0; c < 16; c++) pm = fmaxf(pm, Srow[c]);
            pm = fmaxf(pm, __shfl_xor_sync(0xffffffffu, pm, 1));
            pm = fmaxf(pm, __shfl_xor_sync(0xffffffffu, pm, 2));
            float mo = mrow[r];
            float mn = fmaxf(mo, pm);
            float ps = 0.f;
            #pragma unroll
            for (int c = 0; c < 16; c++) {
                float e = __expf(Srow[c] - mn);
                Srow[c] = e;
                ps += e;
            }
            ps += __shfl_xor_sync(0xffffffffu, ps, 1);
            ps += __shfl_xor_sync(0xffffffffu, ps, 2);
            if (q == 0) {
                float al = __expf(mo - mn);   // mo=-inf on first block -> 0
                lrow[r] = lrow[r] * al + ps;
                mrow[r] = mn;
                arow[r] = al;
            }
        }
        __syncthreads();

        // O = O*alpha + P*V
        #pragma unroll
        for (int i = 0; i < 4; i++) {
            float al = arow[ty * 4 + i];
            #pragma unroll
            for (int j = 0; j < 4; j++) O[i][j] *= al;
        }
        #pragma unroll 4
        for (int c = 0; c < 64; c++) {
            float p[4];
            #pragma unroll
            for (int i = 0; i < 4; i++) p[i] = KtSt[(ty * 4 + i) * 68 + c];
            float4 vf = *(float4*)&Vs[c * 64 + tx * 4];
            float vv[4] = {vf.x, vf.y, vf.z, vf.w};
            #pragma unroll
            for (int i = 0; i < 4; i++)
                #pragma unroll
                for (int j = 0; j < 4; j++)
                    O[i][j] += p[i] * vv[j];
        }
        __syncthreads();
    }

    // epilogue: normalize, apply query mask, write head buffer (B, L, H*DK)
    #pragma unroll
    for (int i = 0; i < 4; i++) {
        int r = ty * 4 + i;
        float sc = mask[(size_t)b * Ll + l0 + r] / lrow[r];
        float4 o4 = make_float4(O[i][0] * sc, O[i][1] * sc,
                                O[i][2] * sc, O[i][3] * sc);
        size_t off = ((size_t)b * Ll + l0 + r) * Ee + (size_t)h * DKk + tx * 4;
        *(float4*)&g_Hd[off] = o4;
    }
}

// ---------------------------------------------------------------------------
// Kernel 3: output projection.
// NOTE: reference's final `out = head @ Wo` contracts Wo's FIRST dim:
//   out[b,l,d] = sum_e head[b,l,e] * Wo[e,d]
// Then transposed to (B, D, L):  out[b,d,l].
// ---------------------------------------------------------------------------
__global__ __launch_bounds__(256) void oproj_kernel(
    const float* __restrict__ Wo, float* __restrict__ out)
{
    __shared__ float As[16][64];   // As[e][d] = Wo[e0+e][d0+d]
    __shared__ float Bs[16][68];   // Bs[e][l] = Hd[b][l0+l][e0+e]

    int b = blockIdx.z;
    int d0 = blockIdx.y * 64, l0 = blockIdx.x * 64;
    int t = threadIdx.x, ty = t >> 4, tx = t & 15;

    float acc[4][4] = {};

    int ea = t >> 4;              // A-load: e index 0..15
    int d4 = (t & 15) * 4;        // A-load: d offset
    int ll = t >> 2;              // B-load: l index 0..63
    int e4 = (t & 3) * 4;         // B-load: e offset

    const float* wop = Wo + (size_t)ea * Dd + d0 + d4;      // + e0*Dd
    const float* hp  = g_Hd + ((size_t)b * Ll + l0 + ll) * Ee + e4;  // + e0

    for (int e0 = 0; e0 < Ee; e0 += 16) {
        *(float4*)&As[ea][d4] = *(const float4*)&wop[(size_t)e0 * Dd];
        float4 b4 = *(const float4*)&hp[e0];
        Bs[e4 + 0][ll] = b4.x;
        Bs[e4 + 1][ll] = b4.y;
        Bs[e4 + 2][ll] = b4.z;
        Bs[e4 + 3][ll] = b4.w;
        __syncthreads();
        #pragma unroll
        for (int c = 0; c < 16; c++) {
            float a[4];
            #pragma unroll
            for (int i = 0; i < 4; i++) a[i] = As[c][ty * 4 + i];
            float4 bf = *(float4*)&Bs[c][tx * 4];
            float bb[4] = {bf.x, bf.y, bf.z, bf.w};
            #pragma unroll
            for (int i = 0; i < 4; i++)
                #pragma unroll
                for (int j = 0; j < 4; j++)
                    acc[i][j] += a[i] * bb[j];
        }
        __syncthreads();
    }

    #pragma unroll
    for (int i = 0; i < 4; i++) {
        size_t off = ((size_t)b * Dd + d0 + ty * 4 + i) * Ll + l0 + tx * 4;
        float4 o4 = make_float4(acc[i][0], acc[i][1], acc[i][2], acc[i][3]);
        *(float4*)&out[off] = o4;
    }
}

// ---------------------------------------------------------------------------
extern "C" void kernel_launch(void* const* d_in, const int* in_sizes, int n_in,
                              void* d_out, int out_size)
{
    const float* x    = (const float*)d_in[0];
    const float* mask = (const float*)d_in[1];
    const float* Wq   = (const float*)d_in[2];
    const float* Wk   = (const float*)d_in[3];
    const float* Wv   = (const float*)d_in[4];
    const float* Wo   = (const float*)d_in[5];
    float* out = (float*)d_out;

    const int FLASH_SMEM = (4096 + 4352 + 4096 + 256) * 4;  // 51200 bytes
    cudaFuncSetAttribute(flash_kernel,
                         cudaFuncAttributeMaxDynamicSharedMemorySize, FLASH_SMEM);

    qkv_kernel<<<dim3(Ll / 64, Bz * Hh), 256>>>(x, Wq, Wk, Wv);
    flash_kernel<<<dim3(Ll / 64, Bz * Hh), 256, FLASH_SMEM>>>(mask);
    oproj_kernel<<<dim3(Ll / 64, Dd / 64, Bz), 256>>>(Wo, out);
}

// round 2
// speedup vs baseline: 1.6508x; 1.6508x over previous
#include <cuda_runtime.h>
#include <math.h>

#define Bz 2
#define Dd 1024
#define Ll 2048
#define Hh 16
#define DKk 64
#define Ee 1024   // H*DK

// Intermediates (no cudaMalloc allowed)
__device__ float g_Q[(size_t)Bz * Hh * Ll * DKk];
__device__ float g_K[(size_t)Bz * Hh * Ll * DKk];
__device__ float g_V[(size_t)Bz * Hh * Ll * DKk];
__device__ float g_Hd[(size_t)Bz * Ll * Ee];

// ---------------------------------------------------------------------------
// Kernel 1: fused QKV projection.
// q[b,h,l,k] = sum_d x[b,d,l] * Wq[h,d,k]   (Q pre-scaled by 1/sqrt(DK))
// Block: 256 threads, computes 64(L) x 64(DK) tile for one (b,h).
// ---------------------------------------------------------------------------
__global__ __launch_bounds__(256) void qkv_kernel(
    const float* __restrict__ x,
    const float* __restrict__ Wq,
    const float* __restrict__ Wk,
    const float* __restrict__ Wv)
{
    __shared__ float xs[16][64], wqs[16][64], wks[16][64], wvs[16][64];
    int bh = blockIdx.y;
    int b = bh >> 4, h = bh & 15;
    int l0 = blockIdx.x * 64;
    int t = threadIdx.x, ty = t >> 4, tx = t & 15;

    float aq[4][4] = {}, ak[4][4] = {}, av[4][4] = {};

    int kc = t >> 4;            // 0..15 (d within chunk)
    int c4 = (t & 15) * 4;      // 0..60

    const float* xp  = x  + ((size_t)b * Dd) * Ll + l0 + c4;
    const float* wqp = Wq + ((size_t)h * Dd) * DKk + c4;
    const float* wkp = Wk + ((size_t)h * Dd) * DKk + c4;
    const float* wvp = Wv + ((size_t)h * Dd) * DKk + c4;

    for (int d0 = 0; d0 < Dd; d0 += 16) {
        *(float4*)&xs[kc][c4]  = *(const float4*)&xp[(size_t)(d0 + kc) * Ll];
        *(float4*)&wqs[kc][c4] = *(const float4*)&wqp[(d0 + kc) * DKk];
        *(float4*)&wks[kc][c4] = *(const float4*)&wkp[(d0 + kc) * DKk];
        *(float4*)&wvs[kc][c4] = *(const float4*)&wvp[(d0 + kc) * DKk];
        __syncthreads();
        #pragma unroll
        for (int c = 0; c < 16; c++) {
            float a[4];
            #pragma unroll
            for (int i = 0; i < 4; i++) a[i] = xs[c][ty * 4 + i];
            float4 fq = *(float4*)&wqs[c][tx * 4];
            float4 fk = *(float4*)&wks[c][tx * 4];
            float4 fv = *(float4*)&wvs[c][tx * 4];
            float bq[4] = {fq.x, fq.y, fq.z, fq.w};
            float bk[4] = {fk.x, fk.y, fk.z, fk.w};
            float bv[4] = {fv.x, fv.y, fv.z, fv.w};
            #pragma unroll
            for (int i = 0; i < 4; i++) {
                #pragma unroll
                for (int j = 0; j < 4; j++) {
                    aq[i][j] += a[i] * bq[j];
                    ak[i][j] += a[i] * bk[j];
                    av[i][j] += a[i] * bv[j];
                }
            }
        }
        __syncthreads();
    }

    size_t obase = ((size_t)bh * Ll + l0 + ty * 4) * DKk + tx * 4;
    #pragma unroll
    for (int i = 0; i < 4; i++) {
        float4 q4 = make_float4(aq[i][0] * 0.125f, aq[i][1] * 0.125f,
                                aq[i][2] * 0.125f, aq[i][3] * 0.125f);
        float4 k4 = make_float4(ak[i][0], ak[i][1], ak[i][2], ak[i][3]);
        float4 v4 = make_float4(av[i][0], av[i][1], av[i][2], av[i][3]);
        *(float4*)&g_Q[obase + (size_t)i * DKk] = q4;
        *(float4*)&g_K[obase + (size_t)i * DKk] = k4;
        *(float4*)&g_V[obase + (size_t)i * DKk] = v4;
    }
}

// ---------------------------------------------------------------------------
// Kernel 2: flash attention per (b,h). Br = Bc = 64, online softmax.
// Key mask -> -1e30 score; query mask applied in epilogue.
// Dynamic smem: Qs[64][64], Kt/St[64][68] (shared), Vs[64][64], 4x[64] aux.
// ---------------------------------------------------------------------------
extern __shared__ float sm_f[];

__global__ __launch_bounds__(256) void flash_kernel(const float* __restrict__ mask)
{
    float* Qs   = sm_f;                       // 4096 floats [row][k]
    float* KtSt = sm_f + 4096;                // 4352 floats [64][68]
    float* Vs   = sm_f + 4096 + 4352;         // 4096 floats [row][k]
    float* mrow = Vs + 4096;                  // 64
    float* lrow = mrow + 64;                  // 64
    float* arow = lrow + 64;                  // 64
    float* kmsk = arow + 64;                  // 64

    int bh = blockIdx.y;
    int b = bh >> 4, h = bh & 15;
    int l0 = blockIdx.x * 64;
    int t = threadIdx.x, ty = t >> 4, tx = t & 15;

    const size_t qbase = ((size_t)bh * Ll + l0) * DKk;
    #pragma unroll
    for (int i = 0; i < 4; i++) {
        int fidx = t + i * 256;
        int r = fidx >> 4, k4 = (fidx & 15) * 4;
        *(float4*)&Qs[r * 64 + k4] = *(const float4*)&g_Q[qbase + (size_t)r * DKk + k4];
    }
    if (t < 64) { mrow[t] = -INFINITY; lrow[t] = 0.f; }

    float O[4][4] = {};

    for (int kb = 0; kb < Ll; kb += 64) {
        const size_t kbase = ((size_t)bh * Ll + kb) * DKk;
        #pragma unroll
        for (int i = 0; i < 4; i++) {
            int fidx = t + i * 256;
            int r = fidx >> 4, k4 = (fidx & 15) * 4;
            float4 kv = *(const float4*)&g_K[kbase + (size_t)r * DKk + k4];
            KtSt[(k4 + 0) * 68 + r] = kv.x;
            KtSt[(k4 + 1) * 68 + r] = kv.y;
            KtSt[(k4 + 2) * 68 + r] = kv.z;
            KtSt[(k4 + 3) * 68 + r] = kv.w;
            *(float4*)&Vs[r * 64 + k4] = *(const float4*)&g_V[kbase + (size_t)r * DKk + k4];
        }
        if (t < 64) kmsk[t] = mask[(size_t)b * Ll + kb + t];
        __syncthreads();

        // S = Q * K^T  (scale already folded into Q)
        float s[4][4] = {};
        #pragma unroll 4
        for (int c = 0; c < 64; c++) {
            float a[4];
            #pragma unroll
            for (int i = 0; i < 4; i++) a[i] = Qs[(ty * 4 + i) * 64 + c];
            float4 kf = *(float4*)&KtSt[c * 68 + tx * 4];
            float bb[4] = {kf.x, kf.y, kf.z, kf.w};
            #pragma unroll
            for (int i = 0; i < 4; i++)
                #pragma unroll
                for (int j = 0; j < 4; j++)
                    s[i][j] += a[i] * bb[j];
        }
        __syncthreads();   // Kt no longer needed; reuse as St

        // masked scores -> St
        float km[4] = {kmsk[tx * 4 + 0], kmsk[tx * 4 + 1],
                       kmsk[tx * 4 + 2], kmsk[tx * 4 + 3]};
        #pragma unroll
        for (int i = 0; i < 4; i++) {
            float4 sv;
            sv.x = (km[0] > 0.5f) ? s[i][0] : -1e30f;
            sv.y = (km[1] > 0.5f) ? s[i][1] : -1e30f;
            sv.z = (km[2] > 0.5f) ? s[i][2] : -1e30f;
            sv.w = (km[3] > 0.5f) ? s[i][3] : -1e30f;
            *(float4*)&KtSt[(ty * 4 + i) * 68 + tx * 4] = sv;
        }
        __syncthreads();

        // online softmax: 4 lanes per row
        {
            int r = t >> 2, q = t & 3;
            float* Srow = &KtSt[r * 68 + q * 16];
            float pm = -INFINITY;
            #pragma unroll
            for (int c = 0; c < 16; c++) pm = fmaxf(pm, Srow[c]);
            pm = fmaxf(pm, __shfl_xor_sync(0xffffffffu, pm, 1));
            pm = fmaxf(pm, __shfl_xor_sync(0xffffffffu, pm, 2));
            float mo = mrow[r];
            float mn = fmaxf(mo, pm);
            float ps = 0.f;
            #pragma unroll
            for (int c = 0; c < 16; c++) {
                float e = __expf(Srow[c] - mn);
                Srow[c] = e;
                ps += e;
            }
            ps += __shfl_xor_sync(0xffffffffu, ps, 1);
            ps += __shfl_xor_sync(0xffffffffu, ps, 2);
            if (q == 0) {
                float al = __expf(mo - mn);   // mo=-inf on first block -> 0
                lrow[r] = lrow[r] * al + ps;
                mrow[r] = mn;
                arow[r] = al;
            }
        }
        __syncthreads();

        // O = O*alpha + P*V
        #pragma unroll
        for (int i = 0; i < 4; i++) {
            float al = arow[ty * 4 + i];
            #pragma unroll
            for (int j = 0; j < 4; j++) O[i][j] *= al;
        }
        #pragma unroll 4
        for (int c = 0; c < 64; c++) {
            float p[4];
            #pragma unroll
            for (int i = 0; i < 4; i++) p[i] = KtSt[(ty * 4 + i) * 68 + c];
            float4 vf = *(float4*)&Vs[c * 64 + tx * 4];
            float vv[4] = {vf.x, vf.y, vf.z, vf.w};
            #pragma unroll
            for (int i = 0; i < 4; i++)
                #pragma unroll
                for (int j = 0; j < 4; j++)
                    O[i][j] += p[i] * vv[j];
        }
        __syncthreads();
    }

    // epilogue: normalize, apply query mask, write head buffer (B, L, H*DK)
    #pragma unroll
    for (int i = 0; i < 4; i++) {
        int r = ty * 4 + i;
        float sc = mask[(size_t)b * Ll + l0 + r] / lrow[r];
        float4 o4 = make_float4(O[i][0] * sc, O[i][1] * sc,
                                O[i][2] * sc, O[i][3] * sc);
        size_t off = ((size_t)b * Ll + l0 + r) * Ee + (size_t)h * DKk + tx * 4;
        *(float4*)&g_Hd[off] = o4;
    }
}

// ---------------------------------------------------------------------------
// Kernel 3: output projection.
// NOTE: reference's final `out = head @ Wo` contracts Wo's FIRST dim:
//   out[b,l,d] = sum_e head[b,l,e] * Wo[e,d]
// Then transposed to (B, D, L):  out[b,d,l].
// ---------------------------------------------------------------------------
__global__ __launch_bounds__(256) void oproj_kernel(
    const float* __restrict__ Wo, float* __restrict__ out)
{
    __shared__ float As[16][64];   // As[e][d] = Wo[e0+e][d0+d]
    __shared__ float Bs[16][68];   // Bs[e][l] = Hd[b][l0+l][e0+e]

    int b = blockIdx.z;
    int d0 = blockIdx.y * 64, l0 = blockIdx.x * 64;
    int t = threadIdx.x, ty = t >> 4, tx = t & 15;

    float acc[4][4] = {};

    int ea = t >> 4;              // A-load: e index 0..15
    int d4 = (t & 15) * 4;        // A-load: d offset
    int ll = t >> 2;              // B-load: l index 0..63
    int e4 = (t & 3) * 4;         // B-load: e offset

    const float* wop = Wo + (size_t)ea * Dd + d0 + d4;      // + e0*Dd
    const float* hp  = g_Hd + ((size_t)b * Ll + l0 + ll) * Ee + e4;  // + e0

    for (int e0 = 0; e0 < Ee; e0 += 16) {
        *(float4*)&As[ea][d4] = *(const float4*)&wop[(size_t)e0 * Dd];
        float4 b4 = *(const float4*)&hp[e0];
        Bs[e4 + 0][ll] = b4.x;
        Bs[e4 + 1][ll] = b4.y;
        Bs[e4 + 2][ll] = b4.z;
        Bs[e4 + 3][ll] = b4.w;
        __syncthreads();
        #pragma unroll
        for (int c = 0; c < 16; c++) {
            float a[4];
            #pragma unroll
            for (int i = 0; i < 4; i++) a[i] = As[c][ty * 4 + i];
            float4 bf = *(float4*)&Bs[c][tx * 4];
            float bb[4] = {bf.x, bf.y, bf.z, bf.w};
            #pragma unroll
            for (int i = 0; i < 4; i++)
                #pragma unroll
                for (int j = 0; j < 4; j++)
                    acc[i][j] += a[i] * bb[j];
        }
        __syncthreads();
    }

    #pragma unroll
    for (int i = 0; i < 4; i++) {
        size_t off = ((size_t)b * Dd + d0 + ty * 4 + i) * Ll + l0 + tx * 4;
        float4 o4 = make_float4(acc[i][0], acc[i][1], acc[i][2], acc[i][3]);
        *(float4*)&out[off] = o4;
    }
}

// ---------------------------------------------------------------------------
extern "C" void kernel_launch(void* const* d_in, const int* in_sizes, int n_in,
                              void* d_out, int out_size)
{
    const float* x    = (const float*)d_in[0];
    const float* mask = (const float*)d_in[1];
    const float* Wq   = (const float*)d_in[2];
    const float* Wk   = (const float*)d_in[3];
    const float* Wv   = (const float*)d_in[4];
    const float* Wo   = (const float*)d_in[5];
    float* out = (float*)d_out;

    const int FLASH_SMEM = (4096 + 4352 + 4096 + 256) * 4;  // 51200 bytes
    cudaFuncSetAttribute(flash_kernel,
                         cudaFuncAttributeMaxDynamicSharedMemorySize, FLASH_SMEM);

    qkv_kernel<<<dim3(Ll / 64, Bz * Hh), 256>>>(x, Wq, Wk, Wv);
    flash_kernel<<<dim3(Ll / 64, Bz * Hh), 256, FLASH_SMEM>>>(mask);
    oproj_kernel<<<dim3(Ll / 64, Dd / 64, Bz), 256>>>(Wo, out);
}

// round 4
// speedup vs baseline: 2.2402x; 1.3570x over previous
#include <cuda_runtime.h>
#include <cuda_bf16.h>
#include <mma.h>
#include <math.h>
#include <stdint.h>
using namespace nvcuda;

#define Bz 2
#define Dd 1024
#define Ll 2048
#define Hh 16
#define DKk 64
#define BH 32
typedef uint32_t u32;

// bf16 hi/lo planes, packed as u32 pairs along the contraction dim
__device__ u32 g_xH[(size_t)Bz*Ll*512],  g_xL[(size_t)Bz*Ll*512];    // [b][l][d/2]
__device__ u32 g_wH[(size_t)3*Hh*Dd*32], g_wL[(size_t)3*Hh*Dd*32];   // [m][h][d][k/2]
__device__ u32 g_woH[(size_t)Dd*512],    g_woL[(size_t)Dd*512];      // [e][d/2]
__device__ u32 g_QH[(size_t)BH*Ll*32],   g_QL[(size_t)BH*Ll*32];     // [bh][l][dk/2]
__device__ u32 g_KH[(size_t)BH*Ll*32],   g_KL[(size_t)BH*Ll*32];
__device__ u32 g_VtH[(size_t)BH*DKk*1024], g_VtL[(size_t)BH*DKk*1024]; // [bh][dk][l/2]
__device__ u32 g_HdH[(size_t)Bz*Ll*512], g_HdL[(size_t)Bz*Ll*512];   // [b][l][e/2]

__device__ __forceinline__ u32 pk(float e, float o) {   // low half = e (even idx)
    u32 d; asm("cvt.rn.bf16x2.f32 %0, %1, %2;" : "=r"(d) : "f"(o), "f"(e)); return d;
}
__device__ __forceinline__ float bhi(float x) { return __bfloat162float(__float2bfloat16_rn(x)); }
__device__ __forceinline__ void mma16816(float* c, const u32* a, u32 b0, u32 b1) {
    asm("mma.sync.aligned.m16n8k16.row.col.f32.bf16.bf16.f32 "
        "{%0,%1,%2,%3},{%4,%5,%6,%7},{%8,%9},{%0,%1,%2,%3};"
        : "+f"(c[0]), "+f"(c[1]), "+f"(c[2]), "+f"(c[3])
        : "r"(a[0]), "r"(a[1]), "r"(a[2]), "r"(a[3]), "r"(b0), "r"(b1));
}

// ---------------- prep: split/transpose to bf16 hi/lo ----------------
__global__ __launch_bounds__(256) void x_split(const float* __restrict__ x) {
    __shared__ float st[64][65];
    int b = blockIdx.z, d0 = blockIdx.y * 64, l0 = blockIdx.x * 64, t = threadIdx.x;
    for (int i = t; i < 64 * 64; i += 256) {
        int dr = i >> 6, lc = i & 63;
        st[dr][lc] = x[((size_t)b * Dd + d0 + dr) * Ll + l0 + lc];
    }
    __syncthreads();
    for (int j = t; j < 64 * 32; j += 256) {
        int l = j >> 5, dp = j & 31;
        float e = st[2 * dp][l], o = st[2 * dp + 1][l];
        float he = bhi(e), ho = bhi(o);
        size_t gi = ((size_t)b * Ll + l0 + l) * 512 + (d0 >> 1) + dp;
        g_xH[gi] = pk(he, ho); g_xL[gi] = pk(e - he, o - ho);
    }
}
__global__ void w_split(const float* __restrict__ Wq, const float* __restrict__ Wk,
                        const float* __restrict__ Wv) {
    size_t n = (size_t)3 * Hh * Dd * 32;
    for (size_t i = (size_t)blockIdx.x * blockDim.x + threadIdx.x; i < n;
         i += (size_t)gridDim.x * blockDim.x) {
        int m = (int)(i / ((size_t)Hh * Dd * 32));
        size_t rem = i % ((size_t)Hh * Dd * 32);
        const float* W = m == 0 ? Wq : (m == 1 ? Wk : Wv);
        float s = (m == 0) ? 0.125f : 1.0f;
        size_t hd = rem >> 5; int p = (int)(rem & 31);
        float a = W[hd * 64 + 2 * p] * s, bb = W[hd * 64 + 2 * p + 1] * s;
        float ha = bhi(a), hb = bhi(bb);
        g_wH[i] = pk(ha, hb); g_wL[i] = pk(a - ha, bb - hb);
    }
}
__global__ void wo_split(const float* __restrict__ Wo) {
    size_t n = (size_t)Dd * 512;
    for (size_t i = (size_t)blockIdx.x * blockDim.x + threadIdx.x; i < n;
         i += (size_t)gridDim.x * blockDim.x) {
        size_t e = i >> 9; int p = (int)(i & 511);
        float a = Wo[e * 1024 + 2 * p], bb = Wo[e * 1024 + 2 * p + 1];
        float ha = bhi(a), hb = bhi(bb);
        g_woH[i] = pk(ha, hb); g_woL[i] = pk(a - ha, bb - hb);
    }
}

// ---------------- QKV projection (wmma) ----------------
// grid (Ll/128, BH, 3mats), 256 threads. C[128 l][64 k] = xT[l,d] @ W[d,k].
__global__ __launch_bounds__(256) void qkv_mma() {
    extern __shared__ u32 smq[];
    u32* xs = smq;            // [128][36] hi; lo at +4608
    u32* ws = smq + 9216;     // [64][36] hi; lo at +2304
    int mat = blockIdx.z, bh = blockIdx.y, b = bh >> 4, h = bh & 15;
    int l0 = blockIdx.x * 128, t = threadIdx.x, w = t >> 5, lane = t & 31;

    wmma::fragment<wmma::accumulator, 16, 16, 16, float> acc[4];
    #pragma unroll
    for (int nf = 0; nf < 4; nf++) wmma::fill_fragment(acc[nf], 0.f);

    const u32* gxH = g_xH + ((size_t)b * Ll + l0) * 512;
    const u32* gxL = g_xL + ((size_t)b * Ll + l0) * 512;
    const u32* gwH = g_wH + (size_t)(mat * Hh + h) * Dd * 32;
    const u32* gwL = g_wL + (size_t)(mat * Hh + h) * Dd * 32;

    for (int d0 = 0; d0 < Dd; d0 += 64) {
        __syncthreads();
        for (int i = t; i < 128 * 32; i += 256) {
            int row = i >> 5, c = i & 31;
            xs[row * 36 + c] = gxH[(size_t)row * 512 + (d0 >> 1) + c];
            xs[4608 + row * 36 + c] = gxL[(size_t)row * 512 + (d0 >> 1) + c];
        }
        for (int i = t; i < 64 * 32; i += 256) {
            int dr = i >> 5, c = i & 31;
            ws[dr * 36 + c] = gwH[(size_t)(d0 + dr) * 32 + c];
            ws[2304 + dr * 36 + c] = gwL[(size_t)(d0 + dr) * 32 + c];
        }
        __syncthreads();
        const __nv_bfloat16* xbH = (const __nv_bfloat16*)xs;
        const __nv_bfloat16* xbL = (const __nv_bfloat16*)(xs + 4608);
        const __nv_bfloat16* wbH = (const __nv_bfloat16*)ws;
        const __nv_bfloat16* wbL = (const __nv_bfloat16*)(ws + 2304);
        #pragma unroll
        for (int kk = 0; kk < 4; kk++) {
            wmma::fragment<wmma::matrix_a, 16, 16, 16, __nv_bfloat16, wmma::row_major> aH, aL;
            wmma::load_matrix_sync(aH, xbH + (w * 16) * 72 + kk * 16, 72);
            wmma::load_matrix_sync(aL, xbL + (w * 16) * 72 + kk * 16, 72);
            #pragma unroll
            for (int nf = 0; nf < 4; nf++) {
                wmma::fragment<wmma::matrix_b, 16, 16, 16, __nv_bfloat16, wmma::row_major> bH, bL;
                wmma::load_matrix_sync(bH, wbH + (kk * 16) * 72 + nf * 16, 72);
                wmma::load_matrix_sync(bL, wbL + (kk * 16) * 72 + nf * 16, 72);
                wmma::mma_sync(acc[nf], aH, bH, acc[nf]);
                wmma::mma_sync(acc[nf], aL, bH, acc[nf]);
                wmma::mma_sync(acc[nf], aH, bL, acc[nf]);
            }
        }
    }
    __syncthreads();
    float* scr = (float*)smq + w * 16 * 76;   // per-warp [16][76]
    #pragma unroll
    for (int nf = 0; nf < 4; nf++)
        wmma::store_matrix_sync(scr + nf * 16, acc[nf], 76, wmma::mem_row_major);
    __syncwarp();

    if (mat < 2) {
        u32* dH = mat ? g_KH : g_QH;
        u32* dL = mat ? g_KL : g_QL;
        int row = lane >> 1, hu = lane & 1;
        #pragma unroll
        for (int j = 0; j < 16; j++) {
            int c = hu * 16 + j;
            float v0 = scr[row * 76 + 2 * c], v1 = scr[row * 76 + 2 * c + 1];
            float h0 = bhi(v0), h1 = bhi(v1);
            size_t gi = ((size_t)bh * Ll + l0 + w * 16 + row) * 32 + c;
            dH[gi] = pk(h0, h1); dL[gi] = pk(v0 - h0, v1 - h1);
        }
    } else {
        #pragma unroll
        for (int half = 0; half < 2; half++) {
            int dk = lane + 32 * half;
            #pragma unroll
            for (int j = 0; j < 8; j++) {
                float v0 = scr[(2 * j) * 76 + dk], v1 = scr[(2 * j + 1) * 76 + dk];
                float h0 = bhi(v0), h1 = bhi(v1);
                size_t gi = ((size_t)bh * DKk + dk) * 1024 + ((l0 + w * 16) >> 1) + j;
                g_VtH[gi] = pk(h0, h1); g_VtL[gi] = pk(v0 - h0, v1 - h1);
            }
        }
    }
}

// ---------------- flash attention (raw mma) ----------------
// grid (Ll/128, BH), 256 threads = 8 warps (4m x 2n). Bc = 64.
__global__ __launch_bounds__(256) void flash_mma(const float* __restrict__ mask) {
    extern __shared__ u32 smf[];
    u32* Qs = smf;                       // [128][36] hi; lo +4608
    u32* Ks = smf + 9216;                // [64][36] hi; lo +2304
    u32* Vt = smf + 13824;               // [64][36] hi; lo +2304
    float* S = (float*)(smf + 18432);    // [128][76]
    u32* PH = smf + 28160;               // [128][44]
    u32* PL = smf + 33792;               // [128][44]
    float* mrow = (float*)(smf + 39424);
    float* lrow = mrow + 128; float* arow = lrow + 128; float* kms = arow + 128;

    int bh = blockIdx.y, b = bh >> 4, h = bh & 15, l0 = blockIdx.x * 128;
    int t = threadIdx.x, w = t >> 5, lane = t & 31, g = lane >> 2, r = lane & 3;
    int m0 = (w >> 1) * 32, n0 = (w & 1) * 32;

    const u32* qH = g_QH + ((size_t)bh * Ll + l0) * 32;
    const u32* qL = g_QL + ((size_t)bh * Ll + l0) * 32;
    for (int i = t; i < 128 * 32; i += 256) {
        int row = i >> 5, c = i & 31;
        Qs[row * 36 + c] = qH[(size_t)row * 32 + c];
        Qs[4608 + row * 36 + c] = qL[(size_t)row * 32 + c];
    }
    if (t < 128) { mrow[t] = -INFINITY; lrow[t] = 0.f; }

    float O[2][4][4];
    #pragma unroll
    for (int mf = 0; mf < 2; mf++)
        #pragma unroll
        for (int nf = 0; nf < 4; nf++)
            #pragma unroll
            for (int c = 0; c < 4; c++) O[mf][nf][c] = 0.f;

    for (int kb = 0; kb < Ll; kb += 64) {
        __syncthreads();
        const u32* kH = g_KH + ((size_t)bh * Ll + kb) * 32;
        const u32* kL = g_KL + ((size_t)bh * Ll + kb) * 32;
        const u32* vH = g_VtH + (size_t)bh * DKk * 1024 + (kb >> 1);
        const u32* vL = g_VtL + (size_t)bh * DKk * 1024 + (kb >> 1);
        for (int i = t; i < 64 * 32; i += 256) {
            int row = i >> 5, c = i & 31;
            Ks[row * 36 + c] = kH[(size_t)row * 32 + c];
            Ks[2304 + row * 36 + c] = kL[(size_t)row * 32 + c];
            Vt[row * 36 + c] = vH[(size_t)row * 1024 + c];
            Vt[2304 + row * 36 + c] = vL[(size_t)row * 1024 + c];
        }
        if (t < 64) kms[t] = mask[(size_t)b * Ll + kb + t];
        __syncthreads();

        // S = Q @ K^T
        float sa[2][4][4];
        #pragma unroll
        for (int mf = 0; mf < 2; mf++)
            #pragma unroll
            for (int nf = 0; nf < 4; nf++)
                #pragma unroll
                for (int c = 0; c < 4; c++) sa[mf][nf][c] = 0.f;
        #pragma unroll
        for (int kk = 0; kk < 4; kk++) {
            u32 aH[2][4], aL[2][4];
            #pragma unroll
            for (int mf = 0; mf < 2; mf++) {
                int rw = (m0 + mf * 16 + g) * 36 + kk * 8;
                aH[mf][0] = Qs[rw + r];       aH[mf][1] = Qs[rw + 288 + r];
                aH[mf][2] = Qs[rw + r + 4];   aH[mf][3] = Qs[rw + 288 + r + 4];
                aL[mf][0] = Qs[4608 + rw + r];     aL[mf][1] = Qs[4608 + rw + 288 + r];
                aL[mf][2] = Qs[4608 + rw + r + 4]; aL[mf][3] = Qs[4608 + rw + 288 + r + 4];
            }
            #pragma unroll
            for (int nf = 0; nf < 4; nf++) {
                int nr = (n0 + nf * 8 + g) * 36 + kk * 8;
                u32 bH0 = Ks[nr + r], bH1 = Ks[nr + r + 4];
                u32 bL0 = Ks[2304 + nr + r], bL1 = Ks[2304 + nr + r + 4];
                #pragma unroll
                for (int mf = 0; mf < 2; mf++) {
                    mma16816(sa[mf][nf], aH[mf], bH0, bH1);
                    mma16816(sa[mf][nf], aL[mf], bH0, bH1);
                    mma16816(sa[mf][nf], aH[mf], bL0, bL1);
                }
            }
        }
        // store S with key mask
        #pragma unroll
        for (int mf = 0; mf < 2; mf++)
            #pragma unroll
            for (int nf = 0; nf < 4; nf++) {
                int row = m0 + mf * 16 + g, col = n0 + nf * 8 + 2 * r;
                bool k0 = kms[col] > 0.5f, k1 = kms[col + 1] > 0.5f;
                S[row * 76 + col]           = k0 ? sa[mf][nf][0] : -1e30f;
                S[row * 76 + col + 1]       = k1 ? sa[mf][nf][1] : -1e30f;
                S[(row + 8) * 76 + col]     = k0 ? sa[mf][nf][2] : -1e30f;
                S[(row + 8) * 76 + col + 1] = k1 ? sa[mf][nf][3] : -1e30f;
            }
        __syncthreads();

        // online softmax: 2 threads per row
        {
            int rr = t >> 1, q = t & 1;
            float* Sr = S + rr * 76 + q * 32;
            float pm = -INFINITY;
            #pragma unroll
            for (int c = 0; c < 32; c++) pm = fmaxf(pm, Sr[c]);
            pm = fmaxf(pm, __shfl_xor_sync(0xffffffffu, pm, 1));
            float mo = mrow[rr], mn = fmaxf(mo, pm), ps = 0.f;
            u32* ph = PH + rr * 44 + q * 16;
            u32* pl = PL + rr * 44 + q * 16;
            #pragma unroll
            for (int j = 0; j < 16; j++) {
                float e0 = __expf(Sr[2 * j] - mn), e1 = __expf(Sr[2 * j + 1] - mn);
                ps += e0 + e1;
                float h0 = bhi(e0), h1 = bhi(e1);
                ph[j] = pk(h0, h1); pl[j] = pk(e0 - h0, e1 - h1);
            }
            ps += __shfl_xor_sync(0xffffffffu, ps, 1);
            if (!q) {
                float al = __expf(mo - mn);
                lrow[rr] = lrow[rr] * al + ps; mrow[rr] = mn; arow[rr] = al;
            }
        }
        __syncthreads();

        // rescale O and accumulate P @ V
        #pragma unroll
        for (int mf = 0; mf < 2; mf++) {
            float a0 = arow[m0 + mf * 16 + g], a1 = arow[m0 + mf * 16 + g + 8];
            #pragma unroll
            for (int nf = 0; nf < 4; nf++) {
                O[mf][nf][0] *= a0; O[mf][nf][1] *= a0;
                O[mf][nf][2] *= a1; O[mf][nf][3] *= a1;
            }
        }
        #pragma unroll
        for (int kk = 0; kk < 4; kk++) {
            u32 aH[2][4], aL[2][4];
            #pragma unroll
            for (int mf = 0; mf < 2; mf++) {
                int rw = (m0 + mf * 16 + g) * 44 + kk * 8;
                aH[mf][0] = PH[rw + r];       aH[mf][1] = PH[rw + 352 + r];
                aH[mf][2] = PH[rw + r + 4];   aH[mf][3] = PH[rw + 352 + r + 4];
                aL[mf][0] = PL[rw + r];       aL[mf][1] = PL[rw + 352 + r];
                aL[mf][2] = PL[rw + r + 4];   aL[mf][3] = PL[rw + 352 + r + 4];
            }
            #pragma unroll
            for (int nf = 0; nf < 4; nf++) {
                int nr = (n0 + nf * 8 + g) * 36 + kk * 8;
                u32 bH0 = Vt[nr + r], bH1 = Vt[nr + r + 4];
                u32 bL0 = Vt[2304 + nr + r], bL1 = Vt[2304 + nr + r + 4];
                #pragma unroll
                for (int mf = 0; mf < 2; mf++) {
                    mma16816(O[mf][nf], aH[mf], bH0, bH1);
                    mma16816(O[mf][nf], aL[mf], bH0, bH1);
                    mma16816(O[mf][nf], aH[mf], bL0, bL1);
                }
            }
        }
    }

    // epilogue: normalize, query mask, write packed Hd
    #pragma unroll
    for (int mf = 0; mf < 2; mf++) {
        int row = m0 + mf * 16 + g;
        float q0 = mask[(size_t)b * Ll + l0 + row] / lrow[row];
        float q1 = mask[(size_t)b * Ll + l0 + row + 8] / lrow[row + 8];
        #pragma unroll
        for (int nf = 0; nf < 4; nf++) {
            float c0 = O[mf][nf][0] * q0, c1 = O[mf][nf][1] * q0;
            float c2 = O[mf][nf][2] * q1, c3 = O[mf][nf][3] * q1;
            size_t gi = ((size_t)b * Ll + l0 + row) * 512 + h * 32 + (n0 >> 1) + nf * 4 + r;
            float h0 = bhi(c0), h1 = bhi(c1);
            g_HdH[gi] = pk(h0, h1); g_HdL[gi] = pk(c0 - h0, c1 - h1);
            float h2 = bhi(c2), h3 = bhi(c3);
            g_HdH[gi + 8 * 512] = pk(h2, h3); g_HdL[gi + 8 * 512] = pk(c2 - h2, c3 - h3);
        }
    }
}

// ---------------- output projection (wmma) ----------------
// grid (Ll/128, Dd/64, Bz), 256 threads. out[b,d,l] = sum_e Hd[b,l,e] Wo[e,d]
__global__ __launch_bounds__(256) void oproj_mma(float* __restrict__ out) {
    extern __shared__ u32 smo[];
    u32* hs = smo;           // [128][36] hi; lo +4608
    u32* ws = smo + 9216;    // [64][36] hi; lo +2304
    int b = blockIdx.z, d0 = blockIdx.y * 64, l0 = blockIdx.x * 128;
    int t = threadIdx.x, w = t >> 5, lane = t & 31;

    wmma::fragment<wmma::accumulator, 16, 16, 16, float> acc[4];
    #pragma unroll
    for (int nf = 0; nf < 4; nf++) wmma::fill_fragment(acc[nf], 0.f);

    for (int e0 = 0; e0 < Dd; e0 += 64) {
        __syncthreads();
        for (int i = t; i < 128 * 32; i += 256) {
            int row = i >> 5, c = i & 31;
            size_t gi = ((size_t)b * Ll + l0 + row) * 512 + (e0 >> 1) + c;
            hs[row * 36 + c] = g_HdH[gi];
            hs[4608 + row * 36 + c] = g_HdL[gi];
        }
        for (int i = t; i < 64 * 32; i += 256) {
            int er = i >> 5, c = i & 31;
            size_t gi = (size_t)(e0 + er) * 512 + (d0 >> 1) + c;
            ws[er * 36 + c] = g_woH[gi];
            ws[2304 + er * 36 + c] = g_woL[gi];
        }
        __syncthreads();
        const __nv_bfloat16* hbH = (const __nv_bfloat16*)hs;
        const __nv_bfloat16* hbL = (const __nv_bfloat16*)(hs + 4608);
        const __nv_bfloat16* wbH = (const __nv_bfloat16*)ws;
        const __nv_bfloat16* wbL = (const __nv_bfloat16*)(ws + 2304);
        #pragma unroll
        for (int kk = 0; kk < 4; kk++) {
            wmma::fragment<wmma::matrix_a, 16, 16, 16, __nv_bfloat16, wmma::row_major> aH, aL;
            wmma::load_matrix_sync(aH, hbH + (w * 16) * 72 + kk * 16, 72);
            wmma::load_matrix_sync(aL, hbL + (w * 16) * 72 + kk * 16, 72);
            #pragma unroll
            for (int nf = 0; nf < 4; nf++) {
                wmma::fragment<wmma::matrix_b, 16, 16, 16, __nv_bfloat16, wmma::row_major> bH, bL;
                wmma::load_matrix_sync(bH, wbH + (kk * 16) * 72 + nf * 16, 72);
                wmma::load_matrix_sync(bL, wbL + (kk * 16) * 72 + nf * 16, 72);
                wmma::mma_sync(acc[nf], aH, bH, acc[nf]);
                wmma::mma_sync(acc[nf], aL, bH, acc[nf]);
                wmma::mma_sync(acc[nf], aH, bL, acc[nf]);
            }
        }
    }
    __syncthreads();
    float* scr = (float*)smo + w * 16 * 76;
    #pragma unroll
    for (int nf = 0; nf < 4; nf++)
        wmma::store_matrix_sync(scr + nf * 16, acc[nf], 76, wmma::mem_row_major);
    __syncwarp();
    for (int i = lane; i < 16 * 64; i += 32) {
        int row = i & 15, dc = i >> 4;
        out[((size_t)b * Dd + d0 + dc) * Ll + l0 + w * 16 + row] = scr[row * 76 + dc];
    }
}

// ---------------------------------------------------------------------------
extern "C" void kernel_launch(void* const* d_in, const int* in_sizes, int n_in,
                              void* d_out, int out_size) {
    const float* x    = (const float*)d_in[0];
    const float* mask = (const float*)d_in[1];
    const float* Wq   = (const float*)d_in[2];
    const float* Wk   = (const float*)d_in[3];
    const float* Wv   = (const float*)d_in[4];
    const float* Wo   = (const float*)d_in[5];
    float* out = (float*)d_out;

    const int QKV_SMEM   = 13824 * 4;   // 55296 B
    const int FLASH_SMEM = 39872 * 4;   // 159488 B
    const int OPROJ_SMEM = 13824 * 4;
    cudaFuncSetAttribute(qkv_mma,   cudaFuncAttributeMaxDynamicSharedMemorySize, QKV_SMEM);
    cudaFuncSetAttribute(flash_mma, cudaFuncAttributeMaxDynamicSharedMemorySize, FLASH_SMEM);
    cudaFuncSetAttribute(oproj_mma, cudaFuncAttributeMaxDynamicSharedMemorySize, OPROJ_SMEM);

    x_split<<<dim3(Ll / 64, Dd / 64, Bz), 256>>>(x);
    w_split<<<1024, 256>>>(Wq, Wk, Wv);
    wo_split<<<512, 256>>>(Wo);
    qkv_mma<<<dim3(Ll / 128, BH, 3), 256, QKV_SMEM>>>();
    flash_mma<<<dim3(Ll / 128, BH), 256, FLASH_SMEM>>>(mask);
    oproj_mma<<<dim3(Ll / 128, Dd / 64, Bz), 256, OPROJ_SMEM>>>(out);
}

// round 5
// speedup vs baseline: 2.8076x; 1.2533x over previous
#include <cuda_runtime.h>
#include <cuda_bf16.h>
#include <math.h>
#include <stdint.h>

#define Bz 2
#define Dd 1024
#define Ll 2048
#define Hh 16
#define DKk 64
#define BH 32
typedef uint32_t u32;

// A-side activations: [b*l][dpair] hi/lo
__device__ u32 g_xH[(size_t)Bz*Ll*512],  g_xL[(size_t)Bz*Ll*512];
// QKV weights transposed: [mat][h][dk][dpair]
__device__ u32 g_wH[(size_t)3*Hh*DKk*512], g_wL[(size_t)3*Hh*DKk*512];
// Wo transposed: [d][epair]
__device__ u32 g_woH[(size_t)Dd*512],    g_woL[(size_t)Dd*512];
// Q,K: [bh][l][dkpair]
__device__ u32 g_QH[(size_t)BH*Ll*32],   g_QL[(size_t)BH*Ll*32];
__device__ u32 g_KH[(size_t)BH*Ll*32],   g_KL[(size_t)BH*Ll*32];
// V transposed: [bh][dk][lpair]
__device__ u32 g_VtH[(size_t)BH*DKk*1024], g_VtL[(size_t)BH*DKk*1024];
// heads: [b*l][epair]
__device__ u32 g_HdH[(size_t)Bz*Ll*512], g_HdL[(size_t)Bz*Ll*512];

extern __shared__ u32 dynsm[];

__device__ __forceinline__ u32 pk(float e, float o) {
    u32 d; asm("cvt.rn.bf16x2.f32 %0, %1, %2;" : "=r"(d) : "f"(o), "f"(e)); return d;
}
__device__ __forceinline__ float bhi(float x) { return __bfloat162float(__float2bfloat16_rn(x)); }
__device__ __forceinline__ void mma16816(float* c, const u32* a, u32 b0, u32 b1) {
    asm("mma.sync.aligned.m16n8k16.row.col.f32.bf16.bf16.f32 "
        "{%0,%1,%2,%3},{%4,%5,%6,%7},{%8,%9},{%0,%1,%2,%3};"
        : "+f"(c[0]), "+f"(c[1]), "+f"(c[2]), "+f"(c[3])
        : "r"(a[0]), "r"(a[1]), "r"(a[2]), "r"(a[3]), "r"(b0), "r"(b1));
}

// ---------------- prep kernels ----------------
__global__ __launch_bounds__(256) void x_split(const float* __restrict__ x) {
    __shared__ float st[64][65];
    int b = blockIdx.z, d0 = blockIdx.y * 64, l0 = blockIdx.x * 64, t = threadIdx.x;
    for (int i = t; i < 64 * 64; i += 256) {
        int dr = i >> 6, lc = i & 63;
        st[dr][lc] = x[((size_t)b * Dd + d0 + dr) * Ll + l0 + lc];
    }
    __syncthreads();
    for (int j = t; j < 64 * 32; j += 256) {
        int l = j >> 5, dp = j & 31;
        float e = st[2 * dp][l], o = st[2 * dp + 1][l];
        float he = bhi(e), ho = bhi(o);
        size_t gi = ((size_t)b * Ll + l0 + l) * 512 + (d0 >> 1) + dp;
        g_xH[gi] = pk(he, ho); g_xL[gi] = pk(e - he, o - ho);
    }
}
// W[h,d,k] -> [mat][h][k][dpair], Q pre-scaled
__global__ __launch_bounds__(256) void w_split_t(const float* __restrict__ Wq,
                                                 const float* __restrict__ Wk,
                                                 const float* __restrict__ Wv) {
    __shared__ float st[64][65];
    int mat = blockIdx.z, h = blockIdx.y, d0 = blockIdx.x * 64, t = threadIdx.x;
    const float* W = mat == 0 ? Wq : (mat == 1 ? Wk : Wv);
    float s = (mat == 0) ? 0.125f : 1.0f;
    for (int i = t; i < 64 * 64; i += 256) {
        int dr = i >> 6, kc = i & 63;
        st[dr][kc] = W[((size_t)h * Dd + d0 + dr) * DKk + kc] * s;
    }
    __syncthreads();
    for (int j = t; j < 64 * 32; j += 256) {
        int k = j >> 5, dp = j & 31;
        float e = st[2 * dp][k], o = st[2 * dp + 1][k];
        float he = bhi(e), ho = bhi(o);
        size_t gi = ((size_t)(mat * Hh + h) * DKk + k) * 512 + (d0 >> 1) + dp;
        g_wH[gi] = pk(he, ho); g_wL[gi] = pk(e - he, o - ho);
    }
}
// Wo[e,d] -> [d][epair]
__global__ __launch_bounds__(256) void wo_split_t(const float* __restrict__ Wo) {
    __shared__ float st[64][65];
    int e0 = blockIdx.y * 64, d0 = blockIdx.x * 64, t = threadIdx.x;
    for (int i = t; i < 64 * 64; i += 256) {
        int er = i >> 6, dc = i & 63;
        st[er][dc] = Wo[((size_t)(e0 + er)) * Dd + d0 + dc];
    }
    __syncthreads();
    for (int j = t; j < 64 * 32; j += 256) {
        int d = j >> 5, ep = j & 31;
        float e = st[2 * ep][d], o = st[2 * ep + 1][d];
        float he = bhi(e), ho = bhi(o);
        size_t gi = ((size_t)(d0 + d)) * 512 + (e0 >> 1) + ep;
        g_woH[gi] = pk(he, ho); g_woL[gi] = pk(e - he, o - ho);
    }
}

// ---------------- fused QKV GEMM: [4096 x 3072] ----------------
// grid (32, 24): y -> mat = y/8, heads sub*2, sub*2+1. 128x128 tile, 8 warps 2m x 4n.
__global__ __launch_bounds__(256, 1) void qkv_gemm() {
    u32* AsH = dynsm;          u32* AsL = dynsm + 4608;
    u32* BsH = dynsm + 9216;   u32* BsL = dynsm + 13824;
    int brow = blockIdx.x * 128;
    int b = brow >> 11, lloc = brow & 2047;
    int mat = blockIdx.y >> 3, sub = blockIdx.y & 7, h0 = sub * 2;
    int t = threadIdx.x, w = t >> 5, lane = t & 31, g = lane >> 2, r = lane & 3;
    int mw = w >> 2, nw = w & 3;
    int m0w = mw * 64, n0w = nw * 32;

    float acc[4][4][4];
    #pragma unroll
    for (int mf = 0; mf < 4; mf++)
        #pragma unroll
        for (int nf = 0; nf < 4; nf++)
            #pragma unroll
            for (int c = 0; c < 4; c++) acc[mf][nf][c] = 0.f;

    const size_t wrowbase = (size_t)(mat * Hh + h0) * DKk * 512;

    for (int d0 = 0; d0 < Dd; d0 += 64) {
        __syncthreads();
        int dp0 = d0 >> 1;
        for (int i = t; i < 1024; i += 256) {
            int row = i >> 3, q = (i & 7) * 4;
            size_t gi = ((size_t)(brow + row)) * 512 + dp0 + q;
            *(uint4*)&AsH[row * 36 + q] = *(const uint4*)&g_xH[gi];
            *(uint4*)&AsL[row * 36 + q] = *(const uint4*)&g_xL[gi];
        }
        for (int i = t; i < 1024; i += 256) {
            int n = i >> 3, q = (i & 7) * 4;
            size_t gi = wrowbase + (size_t)n * 512 + dp0 + q;   // n covers 2 heads x 64 dk
            *(uint4*)&BsH[n * 36 + q] = *(const uint4*)&g_wH[gi];
            *(uint4*)&BsL[n * 36 + q] = *(const uint4*)&g_wL[gi];
        }
        __syncthreads();
        #pragma unroll
        for (int kk = 0; kk < 4; kk++) {
            u32 aH[4][4], aL[4][4];
            #pragma unroll
            for (int mf = 0; mf < 4; mf++) {
                int rw = (m0w + mf * 16 + g) * 36 + kk * 8;
                aH[mf][0] = AsH[rw + r];       aH[mf][1] = AsH[rw + 288 + r];
                aH[mf][2] = AsH[rw + r + 4];   aH[mf][3] = AsH[rw + 288 + r + 4];
                aL[mf][0] = AsL[rw + r];       aL[mf][1] = AsL[rw + 288 + r];
                aL[mf][2] = AsL[rw + r + 4];   aL[mf][3] = AsL[rw + 288 + r + 4];
            }
            #pragma unroll
            for (int nf = 0; nf < 4; nf++) {
                int nr = (n0w + nf * 8 + g) * 36 + kk * 8;
                u32 bH0 = BsH[nr + r], bH1 = BsH[nr + r + 4];
                u32 bL0 = BsL[nr + r], bL1 = BsL[nr + r + 4];
                #pragma unroll
                for (int mf = 0; mf < 4; mf++) {
                    mma16816(acc[mf][nf], aH[mf], bH0, bH1);
                    mma16816(acc[mf][nf], aL[mf], bH0, bH1);
                    mma16816(acc[mf][nf], aH[mf], bL0, bL1);
                }
            }
        }
    }

    // stage to smem, then packed coalesced writeout
    __syncthreads();
    float* Cs = (float*)dynsm; const int CP = 133;
    #pragma unroll
    for (int mf = 0; mf < 4; mf++)
        #pragma unroll
        for (int nf = 0; nf < 4; nf++) {
            int row = m0w + mf * 16 + g, col = n0w + nf * 8 + 2 * r;
            Cs[row * CP + col] = acc[mf][nf][0];
            Cs[row * CP + col + 1] = acc[mf][nf][1];
            Cs[(row + 8) * CP + col] = acc[mf][nf][2];
            Cs[(row + 8) * CP + col + 1] = acc[mf][nf][3];
        }
    __syncthreads();
    if (mat < 2) {
        u32* dH = mat ? g_KH : g_QH;
        u32* dL = mat ? g_KL : g_QL;
        for (int i = t; i < 128 * 64; i += 256) {
            int lr = i >> 6, dp = i & 63;           // n_local pair 2dp,2dp+1
            int head = dp >> 5, dkp = dp & 31;
            float v0 = Cs[lr * CP + 2 * dp], v1 = Cs[lr * CP + 2 * dp + 1];
            float h1 = bhi(v0), h2 = bhi(v1);
            size_t gi = ((size_t)(b * 16 + h0 + head) * Ll + lloc + lr) * 32 + dkp;
            dH[gi] = pk(h1, h2); dL[gi] = pk(v0 - h1, v1 - h2);
        }
    } else {
        for (int i = t; i < 128 * 64; i += 256) {
            int nl = i >> 6, lp = i & 63;           // pair rows 2lp,2lp+1
            int head = nl >> 6, dk = nl & 63;
            float v0 = Cs[(2 * lp) * CP + nl], v1 = Cs[(2 * lp + 1) * CP + nl];
            float h1 = bhi(v0), h2 = bhi(v1);
            size_t gi = ((size_t)(b * 16 + h0 + head) * DKk + dk) * 1024 + (lloc >> 1) + lp;
            g_VtH[gi] = pk(h1, h2); g_VtL[gi] = pk(v0 - h1, v1 - h2);
        }
    }
}

// ---------------- flash attention: register softmax ----------------
// grid (16, 32), 8 warps: 4 m-warps (32 rows) x 2 key-chunk warps (32 keys each).
__global__ __launch_bounds__(256, 1) void flash_mma(const float* __restrict__ mask) {
    u32* QsH = dynsm;           u32* QsL = dynsm + 4608;
    u32* KsH = dynsm + 9216;    u32* KsL = dynsm + 11520;
    u32* VtH = dynsm + 13824;   u32* VtL = dynsm + 16128;
    float* pmax = (float*)(dynsm + 18432);   // [2][128]
    float* psum = pmax + 256;                // [2][128]
    float* mrow = psum + 256;                // [128]
    float* lrow = mrow + 128;                // [128]
    float* kms  = lrow + 128;                // [64]

    int bh = blockIdx.y, b = bh >> 4, h = bh & 15, l0 = blockIdx.x * 128;
    int t = threadIdx.x, w = t >> 5, lane = t & 31, g = lane >> 2, r = lane & 3;
    int mw = w >> 1, kw = w & 1;
    int m0w = mw * 32;

    const u32* qH = g_QH + ((size_t)bh * Ll + l0) * 32;
    const u32* qL = g_QL + ((size_t)bh * Ll + l0) * 32;
    for (int i = t; i < 1024; i += 256) {
        int row = i >> 3, q = (i & 7) * 4;
        *(uint4*)&QsH[row * 36 + q] = *(const uint4*)&qH[(size_t)row * 32 + q];
        *(uint4*)&QsL[row * 36 + q] = *(const uint4*)&qL[(size_t)row * 32 + q];
    }
    if (t < 128) { mrow[t] = -INFINITY; lrow[t] = 0.f; }

    float O[2][8][4];
    #pragma unroll
    for (int mf = 0; mf < 2; mf++)
        #pragma unroll
        for (int nf = 0; nf < 8; nf++)
            #pragma unroll
            for (int c = 0; c < 4; c++) O[mf][nf][c] = 0.f;

    for (int kb = 0; kb < Ll; kb += 64) {
        __syncthreads();
        const u32* kHp = g_KH + ((size_t)bh * Ll + kb) * 32;
        const u32* kLp = g_KL + ((size_t)bh * Ll + kb) * 32;
        const u32* vHp = g_VtH + (size_t)bh * DKk * 1024 + (kb >> 1);
        const u32* vLp = g_VtL + (size_t)bh * DKk * 1024 + (kb >> 1);
        for (int i = t; i < 512; i += 256) {
            int row = i >> 3, q = (i & 7) * 4;
            *(uint4*)&KsH[row * 36 + q] = *(const uint4*)&kHp[(size_t)row * 32 + q];
            *(uint4*)&KsL[row * 36 + q] = *(const uint4*)&kLp[(size_t)row * 32 + q];
            *(uint4*)&VtH[row * 36 + q] = *(const uint4*)&vHp[(size_t)row * 1024 + q];
            *(uint4*)&VtL[row * 36 + q] = *(const uint4*)&vLp[(size_t)row * 1024 + q];
        }
        if (t < 64) kms[t] = mask[(size_t)b * Ll + kb + t];
        __syncthreads();

        // S = Q @ K^T for this warp's 32 keys (koff = kw*32)
        float sa[2][4][4];
        #pragma unroll
        for (int mf = 0; mf < 2; mf++)
            #pragma unroll
            for (int nf = 0; nf < 4; nf++)
                #pragma unroll
                for (int c = 0; c < 4; c++) sa[mf][nf][c] = 0.f;
        #pragma unroll
        for (int kk = 0; kk < 4; kk++) {
            u32 aH[2][4], aL[2][4];
            #pragma unroll
            for (int mf = 0; mf < 2; mf++) {
                int rw = (m0w + mf * 16 + g) * 36 + kk * 8;
                aH[mf][0] = QsH[rw + r];       aH[mf][1] = QsH[rw + 288 + r];
                aH[mf][2] = QsH[rw + r + 4];   aH[mf][3] = QsH[rw + 288 + r + 4];
                aL[mf][0] = QsL[rw + r];       aL[mf][1] = QsL[rw + 288 + r];
                aL[mf][2] = QsL[rw + r + 4];   aL[mf][3] = QsL[rw + 288 + r + 4];
            }
            #pragma unroll
            for (int nf = 0; nf < 4; nf++) {
                int nr = (kw * 32 + nf * 8 + g) * 36 + kk * 8;
                u32 bH0 = KsH[nr + r], bH1 = KsH[nr + r + 4];
                u32 bL0 = KsL[nr + r], bL1 = KsL[nr + r + 4];
                #pragma unroll
                for (int mf = 0; mf < 2; mf++) {
                    mma16816(sa[mf][nf], aH[mf], bH0, bH1);
                    mma16816(sa[mf][nf], aL[mf], bH0, bH1);
                    mma16816(sa[mf][nf], aH[mf], bL0, bL1);
                }
            }
        }
        // key mask + per-warp row max (quad reduce)
        float pmA[2], pmB[2];
        #pragma unroll
        for (int mf = 0; mf < 2; mf++) { pmA[mf] = -INFINITY; pmB[mf] = -INFINITY; }
        #pragma unroll
        for (int nf = 0; nf < 4; nf++) {
            int kc = kw * 32 + nf * 8 + 2 * r;
            bool k0 = kms[kc] > 0.5f, k1 = kms[kc + 1] > 0.5f;
            #pragma unroll
            for (int mf = 0; mf < 2; mf++) {
                if (!k0) { sa[mf][nf][0] = -1e30f; sa[mf][nf][2] = -1e30f; }
                if (!k1) { sa[mf][nf][1] = -1e30f; sa[mf][nf][3] = -1e30f; }
                pmA[mf] = fmaxf(pmA[mf], fmaxf(sa[mf][nf][0], sa[mf][nf][1]));
                pmB[mf] = fmaxf(pmB[mf], fmaxf(sa[mf][nf][2], sa[mf][nf][3]));
            }
        }
        #pragma unroll
        for (int mf = 0; mf < 2; mf++) {
            pmA[mf] = fmaxf(pmA[mf], __shfl_xor_sync(0xffffffffu, pmA[mf], 1));
            pmA[mf] = fmaxf(pmA[mf], __shfl_xor_sync(0xffffffffu, pmA[mf], 2));
            pmB[mf] = fmaxf(pmB[mf], __shfl_xor_sync(0xffffffffu, pmB[mf], 1));
            pmB[mf] = fmaxf(pmB[mf], __shfl_xor_sync(0xffffffffu, pmB[mf], 2));
            if (r == 0) {
                pmax[kw * 128 + m0w + mf * 16 + g] = pmA[mf];
                pmax[kw * 128 + m0w + mf * 16 + g + 8] = pmB[mf];
            }
        }
        __syncthreads();

        // mn, alpha, exp (in place), partial sums
        float mnA[2], mnB[2], alA[2], alB[2], psA[2], psB[2];
        #pragma unroll
        for (int mf = 0; mf < 2; mf++) {
            int row = m0w + mf * 16 + g;
            float moA = mrow[row], moB = mrow[row + 8];
            mnA[mf] = fmaxf(moA, fmaxf(pmax[row], pmax[128 + row]));
            mnB[mf] = fmaxf(moB, fmaxf(pmax[row + 8], pmax[128 + row + 8]));
            alA[mf] = __expf(moA - mnA[mf]); alB[mf] = __expf(moB - mnB[mf]);
            psA[mf] = 0.f; psB[mf] = 0.f;
        }
        #pragma unroll
        for (int nf = 0; nf < 4; nf++)
            #pragma unroll
            for (int mf = 0; mf < 2; mf++) {
                float e0 = __expf(sa[mf][nf][0] - mnA[mf]);
                float e1 = __expf(sa[mf][nf][1] - mnA[mf]);
                float e2 = __expf(sa[mf][nf][2] - mnB[mf]);
                float e3 = __expf(sa[mf][nf][3] - mnB[mf]);
                sa[mf][nf][0] = e0; sa[mf][nf][1] = e1;
                sa[mf][nf][2] = e2; sa[mf][nf][3] = e3;
                psA[mf] += e0 + e1; psB[mf] += e2 + e3;
            }
        #pragma unroll
        for (int mf = 0; mf < 2; mf++) {
            psA[mf] += __shfl_xor_sync(0xffffffffu, psA[mf], 1);
            psA[mf] += __shfl_xor_sync(0xffffffffu, psA[mf], 2);
            psB[mf] += __shfl_xor_sync(0xffffffffu, psB[mf], 1);
            psB[mf] += __shfl_xor_sync(0xffffffffu, psB[mf], 2);
            if (r == 0) {
                psum[kw * 128 + m0w + mf * 16 + g] = psA[mf];
                psum[kw * 128 + m0w + mf * 16 + g + 8] = psB[mf];
            }
        }
        __syncthreads();
        if (t < 128) {
            float mo = mrow[t];
            float mn = fmaxf(mo, fmaxf(pmax[t], pmax[128 + t]));
            float al = __expf(mo - mn);
            lrow[t] = lrow[t] * al + psum[t] + psum[128 + t];
            mrow[t] = mn;
        }
        // rescale O with locally-computed alphas (same formula as update)
        #pragma unroll
        for (int mf = 0; mf < 2; mf++)
            #pragma unroll
            for (int nf = 0; nf < 8; nf++) {
                O[mf][nf][0] *= alA[mf]; O[mf][nf][1] *= alA[mf];
                O[mf][nf][2] *= alB[mf]; O[mf][nf][3] *= alB[mf];
            }
        // PV: P fragments built from exp'ed S accumulators (C-frag == A-frag layout)
        #pragma unroll
        for (int kp = 0; kp < 2; kp++) {
            #pragma unroll
            for (int mf = 0; mf < 2; mf++) {
                float e00 = sa[mf][2 * kp][0], e01 = sa[mf][2 * kp][1];
                float e02 = sa[mf][2 * kp][2], e03 = sa[mf][2 * kp][3];
                float e10 = sa[mf][2 * kp + 1][0], e11 = sa[mf][2 * kp + 1][1];
                float e12 = sa[mf][2 * kp + 1][2], e13 = sa[mf][2 * kp + 1][3];
                float h00 = bhi(e00), h01 = bhi(e01), h02 = bhi(e02), h03 = bhi(e03);
                float h10 = bhi(e10), h11 = bhi(e11), h12 = bhi(e12), h13 = bhi(e13);
                u32 pHf[4] = { pk(h00, h01), pk(h02, h03), pk(h10, h11), pk(h12, h13) };
                u32 pLf[4] = { pk(e00 - h00, e01 - h01), pk(e02 - h02, e03 - h03),
                               pk(e10 - h10, e11 - h11), pk(e12 - h12, e13 - h13) };
                #pragma unroll
                for (int nf = 0; nf < 8; nf++) {
                    int nr = (nf * 8 + g) * 36 + kw * 16 + kp * 8;
                    u32 bH0 = VtH[nr + r], bH1 = VtH[nr + r + 4];
                    u32 bL0 = VtL[nr + r], bL1 = VtL[nr + r + 4];
                    mma16816(O[mf][nf], pHf, bH0, bH1);
                    mma16816(O[mf][nf], pLf, bH0, bH1);
                    mma16816(O[mf][nf], pHf, bL0, bL1);
                }
            }
        }
    }

    // combine the two key-chunk partial O's, normalize, write Hd
    __syncthreads();
    float* Obuf = (float*)dynsm;   // reuse Qs region: 128 x 68
    if (kw == 1) {
        #pragma unroll
        for (int mf = 0; mf < 2; mf++)
            #pragma unroll
            for (int nf = 0; nf < 8; nf++) {
                int row = m0w + mf * 16 + g, dk = nf * 8 + 2 * r;
                Obuf[row * 68 + dk] = O[mf][nf][0];
                Obuf[row * 68 + dk + 1] = O[mf][nf][1];
                Obuf[(row + 8) * 68 + dk] = O[mf][nf][2];
                Obuf[(row + 8) * 68 + dk + 1] = O[mf][nf][3];
            }
    }
    __syncthreads();
    if (kw == 0) {
        #pragma unroll
        for (int mf = 0; mf < 2; mf++) {
            int row = m0w + mf * 16 + g;
            float s0 = mask[(size_t)b * Ll + l0 + row] / lrow[row];
            float s1 = mask[(size_t)b * Ll + l0 + row + 8] / lrow[row + 8];
            #pragma unroll
            for (int nf = 0; nf < 8; nf++) {
                int dk = nf * 8 + 2 * r;
                float c0 = (O[mf][nf][0] + Obuf[row * 68 + dk]) * s0;
                float c1 = (O[mf][nf][1] + Obuf[row * 68 + dk + 1]) * s0;
                float c2 = (O[mf][nf][2] + Obuf[(row + 8) * 68 + dk]) * s1;
                float c3 = (O[mf][nf][3] + Obuf[(row + 8) * 68 + dk + 1]) * s1;
                size_t gi = ((size_t)b * Ll + l0 + row) * 512 + h * 32 + nf * 4 + r;
                float h0 = bhi(c0), h1 = bhi(c1);
                g_HdH[gi] = pk(h0, h1); g_HdL[gi] = pk(c0 - h0, c1 - h1);
                float h2 = bhi(c2), h3 = bhi(c3);
                g_HdH[gi + 8 * 512] = pk(h2, h3);
                g_HdL[gi + 8 * 512] = pk(c2 - h2, c3 - h3);
            }
        }
    }
}

// ---------------- output projection GEMM + transpose ----------------
// grid (32, 8): C[128 l][128 d] = Hd[4096,1024] @ Wo; out[b,d,l]
__global__ __launch_bounds__(256, 1) void oproj_gemm(float* __restrict__ out) {
    u32* AsH = dynsm;          u32* AsL = dynsm + 4608;
    u32* BsH = dynsm + 9216;   u32* BsL = dynsm + 13824;
    int brow = blockIdx.x * 128;
    int b = brow >> 11, lloc = brow & 2047;
    int d0 = blockIdx.y * 128;
    int t = threadIdx.x, w = t >> 5, lane = t & 31, g = lane >> 2, r = lane & 3;
    int mw = w >> 2, nw = w & 3;
    int m0w = mw * 64, n0w = nw * 32;

    float acc[4][4][4];
    #pragma unroll
    for (int mf = 0; mf < 4; mf++)
        #pragma unroll
        for (int nf = 0; nf < 4; nf++)
            #pragma unroll
            for (int c = 0; c < 4; c++) acc[mf][nf][c] = 0.f;

    for (int e0 = 0; e0 < Dd; e0 += 64) {
        __syncthreads();
        int ep0 = e0 >> 1;
        for (int i = t; i < 1024; i += 256) {
            int row = i >> 3, q = (i & 7) * 4;
            size_t gi = ((size_t)(brow + row)) * 512 + ep0 + q;
            *(uint4*)&AsH[row * 36 + q] = *(const uint4*)&g_HdH[gi];
            *(uint4*)&AsL[row * 36 + q] = *(const uint4*)&g_HdL[gi];
        }
        for (int i = t; i < 1024; i += 256) {
            int n = i >> 3, q = (i & 7) * 4;
            size_t gi = ((size_t)(d0 + n)) * 512 + ep0 + q;
            *(uint4*)&BsH[n * 36 + q] = *(const uint4*)&g_woH[gi];
            *(uint4*)&BsL[n * 36 + q] = *(const uint4*)&g_woL[gi];
        }
        __syncthreads();
        #pragma unroll
        for (int kk = 0; kk < 4; kk++) {
            u32 aH[4][4], aL[4][4];
            #pragma unroll
            for (int mf = 0; mf < 4; mf++) {
                int rw = (m0w + mf * 16 + g) * 36 + kk * 8;
                aH[mf][0] = AsH[rw + r];       aH[mf][1] = AsH[rw + 288 + r];
                aH[mf][2] = AsH[rw + r + 4];   aH[mf][3] = AsH[rw + 288 + r + 4];
                aL[mf][0] = AsL[rw + r];       aL[mf][1] = AsL[rw + 288 + r];
                aL[mf][2] = AsL[rw + r + 4];   aL[mf][3] = AsL[rw + 288 + r + 4];
            }
            #pragma unroll
            for (int nf = 0; nf < 4; nf++) {
                int nr = (n0w + nf * 8 + g) * 36 + kk * 8;
                u32 bH0 = BsH[nr + r], bH1 = BsH[nr + r + 4];
                u32 bL0 = BsL[nr + r], bL1 = BsL[nr + r + 4];
                #pragma unroll
                for (int mf = 0; mf < 4; mf++) {
                    mma16816(acc[mf][nf], aH[mf], bH0, bH1);
                    mma16816(acc[mf][nf], aL[mf], bH0, bH1);
                    mma16816(acc[mf][nf], aH[mf], bL0, bL1);
                }
            }
        }
    }

    __syncthreads();
    float* Cs = (float*)dynsm; const int CP = 133;
    #pragma unroll
    for (int mf = 0; mf < 4; mf++)
        #pragma unroll
        for (int nf = 0; nf < 4; nf++) {
            int row = m0w + mf * 16 + g, col = n0w + nf * 8 + 2 * r;
            Cs[row * CP + col] = acc[mf][nf][0];
            Cs[row * CP + col + 1] = acc[mf][nf][1];
            Cs[(row + 8) * CP + col] = acc[mf][nf][2];
            Cs[(row + 8) * CP + col + 1] = acc[mf][nf][3];
        }
    __syncthreads();
    for (int i = t; i < 128 * 128; i += 256) {
        int dc = i >> 7, lc = i & 127;
        out[((size_t)b * Dd + d0 + dc) * Ll + lloc + lc] = Cs[lc * CP + dc];
    }
}

// ---------------------------------------------------------------------------
extern "C" void kernel_launch(void* const* d_in, const int* in_sizes, int n_in,
                              void* d_out, int out_size) {
    const float* x    = (const float*)d_in[0];
    const float* mask = (const float*)d_in[1];
    const float* Wq   = (const float*)d_in[2];
    const float* Wk   = (const float*)d_in[3];
    const float* Wv   = (const float*)d_in[4];
    const float* Wo   = (const float*)d_in[5];
    float* out = (float*)d_out;

    const int GEMM_SMEM  = 18432 * 4;   // 73728 B
    const int FLASH_SMEM = 19264 * 4;   // 77056 B
    cudaFuncSetAttribute(qkv_gemm,  cudaFuncAttributeMaxDynamicSharedMemorySize, GEMM_SMEM);
    cudaFuncSetAttribute(flash_mma, cudaFuncAttributeMaxDynamicSharedMemorySize, FLASH_SMEM);
    cudaFuncSetAttribute(oproj_gemm, cudaFuncAttributeMaxDynamicSharedMemorySize, GEMM_SMEM);

    x_split<<<dim3(Ll / 64, Dd / 64, Bz), 256>>>(x);
    w_split_t<<<dim3(Dd / 64, Hh, 3), 256>>>(Wq, Wk, Wv);
    wo_split_t<<<dim3(Dd / 64, Dd / 64), 256>>>(Wo);
    qkv_gemm<<<dim3(32, 24), 256, GEMM_SMEM>>>();
    flash_mma<<<dim3(Ll / 128, BH), 256, FLASH_SMEM>>>(mask);
    oproj_gemm<<<dim3(32, 8), 256, GEMM_SMEM>>>(out);
}

// round 11
// speedup vs baseline: 3.5545x; 1.2660x over previous
#include <cuda_runtime.h>
#include <cuda_bf16.h>
#include <math.h>
#include <stdint.h>

#define Bz 2
#define Dd 1024
#define Ll 2048
#define Hh 16
#define DKk 64
#define BH 32
typedef uint32_t u32;

// A-side activations: [b*l][dpair] hi/lo
__device__ u32 g_xH[(size_t)Bz*Ll*512],  g_xL[(size_t)Bz*Ll*512];
// QKV weights transposed: [mat][h][dk][dpair]
__device__ u32 g_wH[(size_t)3*Hh*DKk*512], g_wL[(size_t)3*Hh*DKk*512];
// Wo transposed: [d][epair]
__device__ u32 g_woH[(size_t)Dd*512],    g_woL[(size_t)Dd*512];
// Q,K: [bh][l][dkpair]
__device__ u32 g_QH[(size_t)BH*Ll*32],   g_QL[(size_t)BH*Ll*32];
__device__ u32 g_KH[(size_t)BH*Ll*32],   g_KL[(size_t)BH*Ll*32];
// V transposed: [bh][dk][lpair]
__device__ u32 g_VtH[(size_t)BH*DKk*1024], g_VtL[(size_t)BH*DKk*1024];
// heads: [b*l][epair]
__device__ u32 g_HdH[(size_t)Bz*Ll*512], g_HdL[(size_t)Bz*Ll*512];

extern __shared__ u32 dynsm[];

__device__ __forceinline__ u32 pk(float e, float o) {
    u32 d; asm("cvt.rn.bf16x2.f32 %0, %1, %2;" : "=r"(d) : "f"(o), "f"(e)); return d;
}
__device__ __forceinline__ float bhi(float x) { return __bfloat162float(__float2bfloat16_rn(x)); }
__device__ __forceinline__ void mma16816(float* c, const u32* a, u32 b0, u32 b1) {
    asm("mma.sync.aligned.m16n8k16.row.col.f32.bf16.bf16.f32 "
        "{%0,%1,%2,%3},{%4,%5,%6,%7},{%8,%9},{%0,%1,%2,%3};"
        : "+f"(c[0]), "+f"(c[1]), "+f"(c[2]), "+f"(c[3])
        : "r"(a[0]), "r"(a[1]), "r"(a[2]), "r"(a[3]), "r"(b0), "r"(b1));
}
__device__ __forceinline__ u32 smem_u32(const void* p) {
    u32 a;
    asm("{ .reg .u64 t; cvta.to.shared.u64 t, %1; cvt.u32.u64 %0, t; }" : "=r"(a) : "l"(p));
    return a;
}
__device__ __forceinline__ void ldsm4(u32& r0, u32& r1, u32& r2, u32& r3, u32 addr) {
    asm volatile("ldmatrix.sync.aligned.m8n8.x4.shared.b16 {%0,%1,%2,%3}, [%4];"
                 : "=r"(r0), "=r"(r1), "=r"(r2), "=r"(r3) : "r"(addr));
}
__device__ __forceinline__ void cpa16(u32 dst, const void* src) {
    asm volatile("cp.async.cg.shared.global [%0], [%1], 16;" :: "r"(dst), "l"(src));
}

// ---------------- prep kernels ----------------
__global__ __launch_bounds__(256) void x_split(const float* __restrict__ x) {
    __shared__ float st[64][65];
    int b = blockIdx.z, d0 = blockIdx.y * 64, l0 = blockIdx.x * 64, t = threadIdx.x;
    for (int i = t; i < 64 * 64; i += 256) {
        int dr = i >> 6, lc = i & 63;
        st[dr][lc] = x[((size_t)b * Dd + d0 + dr) * Ll + l0 + lc];
    }
    __syncthreads();
    for (int j = t; j < 64 * 32; j += 256) {
        int l = j >> 5, dp = j & 31;
        float e = st[2 * dp][l], o = st[2 * dp + 1][l];
        float he = bhi(e), ho = bhi(o);
        size_t gi = ((size_t)b * Ll + l0 + l) * 512 + (d0 >> 1) + dp;
        g_xH[gi] = pk(he, ho); g_xL[gi] = pk(e - he, o - ho);
    }
}
__global__ __launch_bounds__(256) void w_split_t(const float* __restrict__ Wq,
                                                 const float* __restrict__ Wk,
                                                 const float* __restrict__ Wv) {
    __shared__ float st[64][65];
    int mat = blockIdx.z, h = blockIdx.y, d0 = blockIdx.x * 64, t = threadIdx.x;
    const float* W = mat == 0 ? Wq : (mat == 1 ? Wk : Wv);
    float s = (mat == 0) ? 0.125f : 1.0f;
    for (int i = t; i < 64 * 64; i += 256) {
        int dr = i >> 6, kc = i & 63;
        st[dr][kc] = W[((size_t)h * Dd + d0 + dr) * DKk + kc] * s;
    }
    __syncthreads();
    for (int j = t; j < 64 * 32; j += 256) {
        int k = j >> 5, dp = j & 31;
        float e = st[2 * dp][k], o = st[2 * dp + 1][k];
        float he = bhi(e), ho = bhi(o);
        size_t gi = ((size_t)(mat * Hh + h) * DKk + k) * 512 + (d0 >> 1) + dp;
        g_wH[gi] = pk(he, ho); g_wL[gi] = pk(e - he, o - ho);
    }
}
__global__ __launch_bounds__(256) void wo_split_t(const float* __restrict__ Wo) {
    __shared__ float st[64][65];
    int e0 = blockIdx.y * 64, d0 = blockIdx.x * 64, t = threadIdx.x;
    for (int i = t; i < 64 * 64; i += 256) {
        int er = i >> 6, dc = i & 63;
        st[er][dc] = Wo[((size_t)(e0 + er)) * Dd + d0 + dc];
    }
    __syncthreads();
    for (int j = t; j < 64 * 32; j += 256) {
        int d = j >> 5, ep = j & 31;
        float e = st[2 * ep][d], o = st[2 * ep + 1][d];
        float he = bhi(e), ho = bhi(o);
        size_t gi = ((size_t)(d0 + d)) * 512 + (e0 >> 1) + ep;
        g_woH[gi] = pk(he, ho); g_woL[gi] = pk(e - he, o - ho);
    }
}

// ------------- pipelined 128x128 GEMM body (mma.sync + ldmatrix + cp.async) -------------
// Stage layout (u32): AH[0,4608) AL[4608,9216) BH[9216,13824) BL[13824,18432)
// pitch 36 u32 per row (144B). Two stages: byte stride 73728.
// Result staged to Cs f32 [128][133] at smem base.
#define STG_B 73728
#define PL_AH 0
#define PL_AL 18432
#define PL_BH 36864
#define PL_BL 55296

__device__ __forceinline__ void gemm_issue(const u32* aH, const u32* aL,
                                           const u32* bH, const u32* bL,
                                           u32 smb, int kb) {
    int t = threadIdx.x;
    int kp0 = kb * 32;
    u32 sbase = smb + (kb & 1) * STG_B;
    for (int i = t; i < 1024; i += 256) {
        int row = i >> 3, q = (i & 7) * 4;
        u32 d = sbase + (row * 36 + q) * 4;
        size_t so = (size_t)row * 512 + kp0 + q;
        cpa16(d + PL_AH, &aH[so]);
        cpa16(d + PL_AL, &aL[so]);
        cpa16(d + PL_BH, &bH[so]);
        cpa16(d + PL_BL, &bL[so]);
    }
    asm volatile("cp.async.commit_group;" ::: "memory");
}

__device__ __forceinline__ void gemm_body(const u32* aH, const u32* aL,
                                          const u32* bH, const u32* bL) {
    int t = threadIdx.x, w = t >> 5, lane = t & 31;
    u32 smb = smem_u32(dynsm);
    int mw = w >> 2, nw = w & 3;
    int m0w = mw * 64, n0w = nw * 32;

    // ldmatrix per-lane address components
    int rowA = (lane & 7) + ((lane >> 3) & 1) * 8;   // + matrix row split
    int colA = ((lane >> 4) & 1) * 16;               // k-half
    int rowB = (lane & 7) + ((lane >> 4) & 1) * 8;
    int colB = ((lane >> 3) & 1) * 16;

    float acc[4][4][4];
    #pragma unroll
    for (int mf = 0; mf < 4; mf++)
        #pragma unroll
        for (int nf = 0; nf < 4; nf++)
            #pragma unroll
            for (int c = 0; c < 4; c++) acc[mf][nf][c] = 0.f;

    gemm_issue(aH, aL, bH, bL, smb, 0);
    for (int kb = 0; kb < 16; kb++) {
        __syncthreads();   // protect buffer (kb+1)&1 from in-flight readers
        if (kb < 15) {
            gemm_issue(aH, aL, bH, bL, smb, kb + 1);
            asm volatile("cp.async.wait_group 1;" ::: "memory");
        } else {
            asm volatile("cp.async.wait_group 0;" ::: "memory");
        }
        __syncthreads();

        u32 sb = smb + (kb & 1) * STG_B;
        #pragma unroll
        for (int kk = 0; kk < 4; kk++) {
            u32 aHf[4][4], aLf[4][4];
            #pragma unroll
            for (int mf = 0; mf < 4; mf++) {
                u32 adr = sb + PL_AH + (u32)(m0w + mf * 16 + rowA) * 144 + kk * 32 + colA;
                ldsm4(aHf[mf][0], aHf[mf][1], aHf[mf][2], aHf[mf][3], adr);
                ldsm4(aLf[mf][0], aLf[mf][1], aLf[mf][2], aLf[mf][3], adr + PL_AL);
            }
            u32 bHf[4][2], bLf[4][2];
            #pragma unroll
            for (int nfp = 0; nfp < 2; nfp++) {
                u32 adr = sb + PL_BH + (u32)(n0w + nfp * 16 + rowB) * 144 + kk * 32 + colB;
                ldsm4(bHf[2*nfp][0], bHf[2*nfp][1], bHf[2*nfp+1][0], bHf[2*nfp+1][1], adr);
                ldsm4(bLf[2*nfp][0], bLf[2*nfp][1], bLf[2*nfp+1][0], bLf[2*nfp+1][1],
                      adr + (PL_BL - PL_BH));
            }
            #pragma unroll
            for (int nf = 0; nf < 4; nf++)
                #pragma unroll
                for (int mf = 0; mf < 4; mf++) {
                    mma16816(acc[mf][nf], aHf[mf], bHf[nf][0], bHf[nf][1]);
                    mma16816(acc[mf][nf], aLf[mf], bHf[nf][0], bHf[nf][1]);
                    mma16816(acc[mf][nf], aHf[mf], bLf[nf][0], bLf[nf][1]);
                }
        }
    }

    // stage accumulators to Cs [128][133]
    __syncthreads();
    float* Cs = (float*)dynsm; const int CP = 133;
    int g = lane >> 2, r = lane & 3;
    #pragma unroll
    for (int mf = 0; mf < 4; mf++)
        #pragma unroll
        for (int nf = 0; nf < 4; nf++) {
            int row = m0w + mf * 16 + g, col = n0w + nf * 8 + 2 * r;
            Cs[row * CP + col] = acc[mf][nf][0];
            Cs[row * CP + col + 1] = acc[mf][nf][1];
            Cs[(row + 8) * CP + col] = acc[mf][nf][2];
            Cs[(row + 8) * CP + col + 1] = acc[mf][nf][3];
        }
    __syncthreads();
}

// ---------------- fused QKV GEMM ----------------
// grid (32, 24): y -> mat=y/8, 2 heads per block; 128(l) x 128(2*dk) tile
__global__ __launch_bounds__(256, 1) void qkv_gemm() {
    int brow = blockIdx.x * 128;
    int b = brow >> 11, lloc = brow & 2047;
    int mat = blockIdx.y >> 3, h0 = (blockIdx.y & 7) * 2;
    int t = threadIdx.x;

    const size_t wbase = (size_t)(mat * Hh + h0) * DKk * 512;
    gemm_body(g_xH + (size_t)brow * 512, g_xL + (size_t)brow * 512,
              g_wH + wbase, g_wL + wbase);

    float* Cs = (float*)dynsm; const int CP = 133;
    if (mat < 2) {
        u32* dH = mat ? g_KH : g_QH;
        u32* dL = mat ? g_KL : g_QL;
        for (int i = t; i < 128 * 64; i += 256) {
            int lr = i >> 6, dp = i & 63;
            int head = dp >> 5, dkp = dp & 31;
            float v0 = Cs[lr * CP + 2 * dp], v1 = Cs[lr * CP + 2 * dp + 1];
            float h1 = bhi(v0), h2 = bhi(v1);
            size_t gi = ((size_t)(b * 16 + h0 + head) * Ll + lloc + lr) * 32 + dkp;
            dH[gi] = pk(h1, h2); dL[gi] = pk(v0 - h1, v1 - h2);
        }
    } else {
        for (int i = t; i < 128 * 64; i += 256) {
            int nl = i >> 6, lp = i & 63;
            int head = nl >> 6, dk = nl & 63;
            float v0 = Cs[(2 * lp) * CP + nl], v1 = Cs[(2 * lp + 1) * CP + nl];
            float h1 = bhi(v0), h2 = bhi(v1);
            size_t gi = ((size_t)(b * 16 + h0 + head) * DKk + dk) * 1024 + (lloc >> 1) + lp;
            g_VtH[gi] = pk(h1, h2); g_VtL[gi] = pk(v0 - h1, v1 - h2);
        }
    }
}

// ---------------- output projection ----------------
// grid (32, 8): 128(l) x 128(d); out[b,d,l]
__global__ __launch_bounds__(256, 1) void oproj_gemm(float* __restrict__ out) {
    int brow = blockIdx.x * 128;
    int b = brow >> 11, lloc = brow & 2047;
    int d0 = blockIdx.y * 128;
    int t = threadIdx.x;

    gemm_body(g_HdH + (size_t)brow * 512, g_HdL + (size_t)brow * 512,
              g_woH + (size_t)d0 * 512, g_woL + (size_t)d0 * 512);

    float* Cs = (float*)dynsm; const int CP = 133;
    for (int i = t; i < 128 * 128; i += 256) {
        int dc = i >> 7, lc = i & 127;
        out[((size_t)b * Dd + d0 + dc) * Ll + lloc + lc] = Cs[lc * CP + dc];
    }
}

// ---------------- flash attention (mma.sync, register softmax) ----------------
__global__ __launch_bounds__(256, 1) void flash_mma(const float* __restrict__ mask) {
    u32* QsH = dynsm;           u32* QsL = dynsm + 4608;
    u32* KsH = dynsm + 9216;    u32* KsL = dynsm + 11520;
    u32* VtH = dynsm + 13824;   u32* VtL = dynsm + 16128;
    float* pmax = (float*)(dynsm + 18432);
    float* psum = pmax + 256;
    float* mrow = psum + 256;
    float* lrow = mrow + 128;
    float* kms  = lrow + 128;

    int bh = blockIdx.y, b = bh >> 4, h = bh & 15, l0 = blockIdx.x * 128;
    int t = threadIdx.x, w = t >> 5, lane = t & 31, g = lane >> 2, r = lane & 3;
    int mw = w >> 1, kw = w & 1;
    int m0w = mw * 32;

    const u32* qH = g_QH + ((size_t)bh * Ll + l0) * 32;
    const u32* qL = g_QL + ((size_t)bh * Ll + l0) * 32;
    for (int i = t; i < 1024; i += 256) {
        int row = i >> 3, q = (i & 7) * 4;
        *(uint4*)&QsH[row * 36 + q] = *(const uint4*)&qH[(size_t)row * 32 + q];
        *(uint4*)&QsL[row * 36 + q] = *(const uint4*)&qL[(size_t)row * 32 + q];
    }
    if (t < 128) { mrow[t] = -INFINITY; lrow[t] = 0.f; }

    float O[2][8][4];
    #pragma unroll
    for (int mf = 0; mf < 2; mf++)
        #pragma unroll
        for (int nf = 0; nf < 8; nf++)
            #pragma unroll
            for (int c = 0; c < 4; c++) O[mf][nf][c] = 0.f;

    for (int kb = 0; kb < Ll; kb += 64) {
        __syncthreads();
        const u32* kHp = g_KH + ((size_t)bh * Ll + kb) * 32;
        const u32* kLp = g_KL + ((size_t)bh * Ll + kb) * 32;
        const u32* vHp = g_VtH + (size_t)bh * DKk * 1024 + (kb >> 1);
        const u32* vLp = g_VtL + (size_t)bh * DKk * 1024 + (kb >> 1);
        for (int i = t; i < 512; i += 256) {
            int row = i >> 3, q = (i & 7) * 4;
            *(uint4*)&KsH[row * 36 + q] = *(const uint4*)&kHp[(size_t)row * 32 + q];
            *(uint4*)&KsL[row * 36 + q] = *(const uint4*)&kLp[(size_t)row * 32 + q];
            *(uint4*)&VtH[row * 36 + q] = *(const uint4*)&vHp[(size_t)row * 1024 + q];
            *(uint4*)&VtL[row * 36 + q] = *(const uint4*)&vLp[(size_t)row * 1024 + q];
        }
        if (t < 64) kms[t] = mask[(size_t)b * Ll + kb + t];
        __syncthreads();

        float sa[2][4][4];
        #pragma unroll
        for (int mf = 0; mf < 2; mf++)
            #pragma unroll
            for (int nf = 0; nf < 4; nf++)
                #pragma unroll
                for (int c = 0; c < 4; c++) sa[mf][nf][c] = 0.f;
        #pragma unroll
        for (int kk = 0; kk < 4; kk++) {
            u32 aH[2][4], aL[2][4];
            #pragma unroll
            for (int mf = 0; mf < 2; mf++) {
                int rw = (m0w + mf * 16 + g) * 36 + kk * 8;
                aH[mf][0] = QsH[rw + r];       aH[mf][1] = QsH[rw + 288 + r];
                aH[mf][2] = QsH[rw + r + 4];   aH[mf][3] = QsH[rw + 288 + r + 4];
                aL[mf][0] = QsL[rw + r];       aL[mf][1] = QsL[rw + 288 + r];
                aL[mf][2] = QsL[rw + r + 4];   aL[mf][3] = QsL[rw + 288 + r + 4];
            }
            #pragma unroll
            for (int nf = 0; nf < 4; nf++) {
                int nr = (kw * 32 + nf * 8 + g) * 36 + kk * 8;
                u32 bH0 = KsH[nr + r], bH1 = KsH[nr + r + 4];
                u32 bL0 = KsL[nr + r], bL1 = KsL[nr + r + 4];
                #pragma unroll
                for (int mf = 0; mf < 2; mf++) {
                    mma16816(sa[mf][nf], aH[mf], bH0, bH1);
                    mma16816(sa[mf][nf], aL[mf], bH0, bH1);
                    mma16816(sa[mf][nf], aH[mf], bL0, bL1);
                }
            }
        }
        float pmA[2], pmB[2];
        #pragma unroll
        for (int mf = 0; mf < 2; mf++) { pmA[mf] = -INFINITY; pmB[mf] = -INFINITY; }
        #pragma unroll
        for (int nf = 0; nf < 4; nf++) {
            int kc = kw * 32 + nf * 8 + 2 * r;
            bool k0 = kms[kc] > 0.5f, k1 = kms[kc + 1] > 0.5f;
            #pragma unroll
            for (int mf = 0; mf < 2; mf++) {
                if (!k0) { sa[mf][nf][0] = -1e30f; sa[mf][nf][2] = -1e30f; }
                if (!k1) { sa[mf][nf][1] = -1e30f; sa[mf][nf][3] = -1e30f; }
                pmA[mf] = fmaxf(pmA[mf], fmaxf(sa[mf][nf][0], sa[mf][nf][1]));
                pmB[mf] = fmaxf(pmB[mf], fmaxf(sa[mf][nf][2], sa[mf][nf][3]));
            }
        }
        #pragma unroll
        for (int mf = 0; mf < 2; mf++) {
            pmA[mf] = fmaxf(pmA[mf], __shfl_xor_sync(0xffffffffu, pmA[mf], 1));
            pmA[mf] = fmaxf(pmA[mf], __shfl_xor_sync(0xffffffffu, pmA[mf], 2));
            pmB[mf] = fmaxf(pmB[mf], __shfl_xor_sync(0xffffffffu, pmB[mf], 1));
            pmB[mf] = fmaxf(pmB[mf], __shfl_xor_sync(0xffffffffu, pmB[mf], 2));
            if (r == 0) {
                pmax[kw * 128 + m0w + mf * 16 + g] = pmA[mf];
                pmax[kw * 128 + m0w + mf * 16 + g + 8] = pmB[mf];
            }
        }
        __syncthreads();

        float mnA[2], mnB[2], alA[2], alB[2], psA[2], psB[2];
        #pragma unroll
        for (int mf = 0; mf < 2; mf++) {
            int row = m0w + mf * 16 + g;
            float moA = mrow[row], moB = mrow[row + 8];
            mnA[mf] = fmaxf(moA, fmaxf(pmax[row], pmax[128 + row]));
            mnB[mf] = fmaxf(moB, fmaxf(pmax[row + 8], pmax[128 + row + 8]));
            alA[mf] = __expf(moA - mnA[mf]); alB[mf] = __expf(moB - mnB[mf]);
            psA[mf] = 0.f; psB[mf] = 0.f;
        }
        #pragma unroll
        for (int nf = 0; nf < 4; nf++)
            #pragma unroll
            for (int mf = 0; mf < 2; mf++) {
                float e0 = __expf(sa[mf][nf][0] - mnA[mf]);
                float e1 = __expf(sa[mf][nf][1] - mnA[mf]);
                float e2 = __expf(sa[mf][nf][2] - mnB[mf]);
                float e3 = __expf(sa[mf][nf][3] - mnB[mf]);
                sa[mf][nf][0] = e0; sa[mf][nf][1] = e1;
                sa[mf][nf][2] = e2; sa[mf][nf][3] = e3;
                psA[mf] += e0 + e1; psB[mf] += e2 + e3;
            }
        #pragma unroll
        for (int mf = 0; mf < 2; mf++) {
            psA[mf] += __shfl_xor_sync(0xffffffffu, psA[mf], 1);
            psA[mf] += __shfl_xor_sync(0xffffffffu, psA[mf], 2);
            psB[mf] += __shfl_xor_sync(0xffffffffu, psB[mf], 1);
            psB[mf] += __shfl_xor_sync(0xffffffffu, psB[mf], 2);
            if (r == 0) {
                psum[kw * 128 + m0w + mf * 16 + g] = psA[mf];
                psum[kw * 128 + m0w + mf * 16 + g + 8] = psB[mf];
            }
        }
        __syncthreads();
        if (t < 128) {
            float mo = mrow[t];
            float mn = fmaxf(mo, fmaxf(pmax[t], pmax[128 + t]));
            float al = __expf(mo - mn);
            lrow[t] = lrow[t] * al + psum[t] + psum[128 + t];
            mrow[t] = mn;
        }
        #pragma unroll
        for (int mf = 0; mf < 2; mf++)
            #pragma unroll
            for (int nf = 0; nf < 8; nf++) {
                O[mf][nf][0] *= alA[mf]; O[mf][nf][1] *= alA[mf];
                O[mf][nf][2] *= alB[mf]; O[mf][nf][3] *= alB[mf];
            }
        #pragma unroll
        for (int kp = 0; kp < 2; kp++) {
            #pragma unroll
            for (int mf = 0; mf < 2; mf++) {
                float e00 = sa[mf][2 * kp][0], e01 = sa[mf][2 * kp][1];
                float e02 = sa[mf][2 * kp][2], e03 = sa[mf][2 * kp][3];
                float e10 = sa[mf][2 * kp + 1][0], e11 = sa[mf][2 * kp + 1][1];
                float e12 = sa[mf][2 * kp + 1][2], e13 = sa[mf][2 * kp + 1][3];
                float h00 = bhi(e00), h01 = bhi(e01), h02 = bhi(e02), h03 = bhi(e03);
                float h10 = bhi(e10), h11 = bhi(e11), h12 = bhi(e12), h13 = bhi(e13);
                u32 pHf[4] = { pk(h00, h01), pk(h02, h03), pk(h10, h11), pk(h12, h13) };
                u32 pLf[4] = { pk(e00 - h00, e01 - h01), pk(e02 - h02, e03 - h03),
                               pk(e10 - h10, e11 - h11), pk(e12 - h12, e13 - h13) };
                #pragma unroll
                for (int nf = 0; nf < 8; nf++) {
                    int nr = (nf * 8 + g) * 36 + kw * 16 + kp * 8;
                    u32 bH0 = VtH[nr + r], bH1 = VtH[nr + r + 4];
                    u32 bL0 = VtL[nr + r], bL1 = VtL[nr + r + 4];
                    mma16816(O[mf][nf], pHf, bH0, bH1);
                    mma16816(O[mf][nf], pLf, bH0, bH1);
                    mma16816(O[mf][nf], pHf, bL0, bL1);
                }
            }
        }
    }

    __syncthreads();
    float* Obuf = (float*)dynsm;
    if (kw == 1) {
        #pragma unroll
        for (int mf = 0; mf < 2; mf++)
            #pragma unroll
            for (int nf = 0; nf < 8; nf++) {
                int row = m0w + mf * 16 + g, dk = nf * 8 + 2 * r;
                Obuf[row * 68 + dk] = O[mf][nf][0];
                Obuf[row * 68 + dk + 1] = O[mf][nf][1];
                Obuf[(row + 8) * 68 + dk] = O[mf][nf][2];
                Obuf[(row + 8) * 68 + dk + 1] = O[mf][nf][3];
            }
    }
    __syncthreads();
    if (kw == 0) {
        #pragma unroll
        for (int mf = 0; mf < 2; mf++) {
            int row = m0w + mf * 16 + g;
            float s0 = mask[(size_t)b * Ll + l0 + row] / lrow[row];
            float s1 = mask[(size_t)b * Ll + l0 + row + 8] / lrow[row + 8];
            #pragma unroll
            for (int nf = 0; nf < 8; nf++) {
                int dk = nf * 8 + 2 * r;
                float c0 = (O[mf][nf][0] + Obuf[row * 68 + dk]) * s0;
                float c1 = (O[mf][nf][1] + Obuf[row * 68 + dk + 1]) * s0;
                float c2 = (O[mf][nf][2] + Obuf[(row + 8) * 68 + dk]) * s1;
                float c3 = (O[mf][nf][3] + Obuf[(row + 8) * 68 + dk + 1]) * s1;
                size_t gi = ((size_t)b * Ll + l0 + row) * 512 + h * 32 + nf * 4 + r;
                float h0 = bhi(c0), h1 = bhi(c1);
                g_HdH[gi] = pk(h0, h1); g_HdL[gi] = pk(c0 - h0, c1 - h1);
                float h2 = bhi(c2), h3 = bhi(c3);
                g_HdH[gi + 8 * 512] = pk(h2, h3);
                g_HdL[gi + 8 * 512] = pk(c2 - h2, c3 - h3);
            }
        }
    }
}

// ---------------------------------------------------------------------------
extern "C" void kernel_launch(void* const* d_in, const int* in_sizes, int n_in,
                              void* d_out, int out_size) {
    const float* x    = (const float*)d_in[0];
    const float* mask = (const float*)d_in[1];
    const float* Wq   = (const float*)d_in[2];
    const float* Wk   = (const float*)d_in[3];
    const float* Wv   = (const float*)d_in[4];
    const float* Wo   = (const float*)d_in[5];
    float* out = (float*)d_out;

    const int GEMM_SMEM  = 2 * STG_B;    // 147456 B
    const int FLASH_SMEM = 19264 * 4;    // 77056 B
    cudaFuncSetAttribute(qkv_gemm,  cudaFuncAttributeMaxDynamicSharedMemorySize, GEMM_SMEM);
    cudaFuncSetAttribute(oproj_gemm, cudaFuncAttributeMaxDynamicSharedMemorySize, GEMM_SMEM);
    cudaFuncSetAttribute(flash_mma, cudaFuncAttributeMaxDynamicSharedMemorySize, FLASH_SMEM);

    x_split<<<dim3(Ll / 64, Dd / 64, Bz), 256>>>(x);
    w_split_t<<<dim3(Dd / 64, Hh, 3), 256>>>(Wq, Wk, Wv);
    wo_split_t<<<dim3(Dd / 64, Dd / 64), 256>>>(Wo);
    qkv_gemm<<<dim3(32, 24), 256, GEMM_SMEM>>>();
    flash_mma<<<dim3(Ll / 128, BH), 256, FLASH_SMEM>>>(mask);
    oproj_gemm<<<dim3(32, 8), 256, GEMM_SMEM>>>(out);
}

// round 12
// speedup vs baseline: 4.2653x; 1.2000x over previous
#include <cuda_runtime.h>
#include <cuda_bf16.h>
#include <math.h>
#include <stdint.h>

#define Bz 2
#define Dd 1024
#define Ll 2048
#define Hh 16
#define DKk 64
#define BH 32
typedef uint32_t u32;

// A-side activations: [b*l][dpair] hi/lo
__device__ u32 g_xH[(size_t)Bz*Ll*512],  g_xL[(size_t)Bz*Ll*512];
// QKV weights transposed: [mat][h][dk][dpair]
__device__ u32 g_wH[(size_t)3*Hh*DKk*512], g_wL[(size_t)3*Hh*DKk*512];
// Wo transposed: [d][epair]
__device__ u32 g_woH[(size_t)Dd*512],    g_woL[(size_t)Dd*512];
// Q,K: [bh][l][dkpair]
__device__ u32 g_QH[(size_t)BH*Ll*32],   g_QL[(size_t)BH*Ll*32];
__device__ u32 g_KH[(size_t)BH*Ll*32],   g_KL[(size_t)BH*Ll*32];
// V transposed: [bh][dk][lpair]
__device__ u32 g_VtH[(size_t)BH*DKk*1024], g_VtL[(size_t)BH*DKk*1024];
// heads: [b*l][epair]
__device__ u32 g_HdH[(size_t)Bz*Ll*512], g_HdL[(size_t)Bz*Ll*512];

extern __shared__ u32 dynsm[];

__device__ __forceinline__ u32 pk(float e, float o) {
    u32 d; asm("cvt.rn.bf16x2.f32 %0, %1, %2;" : "=r"(d) : "f"(o), "f"(e)); return d;
}
__device__ __forceinline__ float bhi(float x) { return __bfloat162float(__float2bfloat16_rn(x)); }
__device__ __forceinline__ void mma16816(float* c, const u32* a, u32 b0, u32 b1) {
    asm("mma.sync.aligned.m16n8k16.row.col.f32.bf16.bf16.f32 "
        "{%0,%1,%2,%3},{%4,%5,%6,%7},{%8,%9},{%0,%1,%2,%3};"
        : "+f"(c[0]), "+f"(c[1]), "+f"(c[2]), "+f"(c[3])
        : "r"(a[0]), "r"(a[1]), "r"(a[2]), "r"(a[3]), "r"(b0), "r"(b1));
}
__device__ __forceinline__ u32 smem_u32(const void* p) {
    u32 a;
    asm("{ .reg .u64 t; cvta.to.shared.u64 t, %1; cvt.u32.u64 %0, t; }" : "=r"(a) : "l"(p));
    return a;
}
__device__ __forceinline__ void ldsm4(u32& r0, u32& r1, u32& r2, u32& r3, u32 addr) {
    asm volatile("ldmatrix.sync.aligned.m8n8.x4.shared.b16 {%0,%1,%2,%3}, [%4];"
                 : "=r"(r0), "=r"(r1), "=r"(r2), "=r"(r3) : "r"(addr));
}
__device__ __forceinline__ void cpa16(u32 dst, const void* src) {
    asm volatile("cp.async.cg.shared.global [%0], [%1], 16;" :: "r"(dst), "l"(src));
}

// ---------------- prep kernels ----------------
__global__ __launch_bounds__(256) void x_split(const float* __restrict__ x) {
    __shared__ float st[64][65];
    int b = blockIdx.z, d0 = blockIdx.y * 64, l0 = blockIdx.x * 64, t = threadIdx.x;
    for (int i = t; i < 64 * 64; i += 256) {
        int dr = i >> 6, lc = i & 63;
        st[dr][lc] = x[((size_t)b * Dd + d0 + dr) * Ll + l0 + lc];
    }
    __syncthreads();
    for (int j = t; j < 64 * 32; j += 256) {
        int l = j >> 5, dp = j & 31;
        float e = st[2 * dp][l], o = st[2 * dp + 1][l];
        float he = bhi(e), ho = bhi(o);
        size_t gi = ((size_t)b * Ll + l0 + l) * 512 + (d0 >> 1) + dp;
        g_xH[gi] = pk(he, ho); g_xL[gi] = pk(e - he, o - ho);
    }
}
__global__ __launch_bounds__(256) void w_split_t(const float* __restrict__ Wq,
                                                 const float* __restrict__ Wk,
                                                 const float* __restrict__ Wv) {
    __shared__ float st[64][65];
    int mat = blockIdx.z, h = blockIdx.y, d0 = blockIdx.x * 64, t = threadIdx.x;
    const float* W = mat == 0 ? Wq : (mat == 1 ? Wk : Wv);
    float s = (mat == 0) ? 0.125f : 1.0f;
    for (int i = t; i < 64 * 64; i += 256) {
        int dr = i >> 6, kc = i & 63;
        st[dr][kc] = W[((size_t)h * Dd + d0 + dr) * DKk + kc] * s;
    }
    __syncthreads();
    for (int j = t; j < 64 * 32; j += 256) {
        int k = j >> 5, dp = j & 31;
        float e = st[2 * dp][k], o = st[2 * dp + 1][k];
        float he = bhi(e), ho = bhi(o);
        size_t gi = ((size_t)(mat * Hh + h) * DKk + k) * 512 + (d0 >> 1) + dp;
        g_wH[gi] = pk(he, ho); g_wL[gi] = pk(e - he, o - ho);
    }
}
__global__ __launch_bounds__(256) void wo_split_t(const float* __restrict__ Wo) {
    __shared__ float st[64][65];
    int e0 = blockIdx.y * 64, d0 = blockIdx.x * 64, t = threadIdx.x;
    for (int i = t; i < 64 * 64; i += 256) {
        int er = i >> 6, dc = i & 63;
        st[er][dc] = Wo[((size_t)(e0 + er)) * Dd + d0 + dc];
    }
    __syncthreads();
    for (int j = t; j < 64 * 32; j += 256) {
        int d = j >> 5, ep = j & 31;
        float e = st[2 * ep][d], o = st[2 * ep + 1][d];
        float he = bhi(e), ho = bhi(o);
        size_t gi = ((size_t)(d0 + d)) * 512 + (e0 >> 1) + ep;
        g_woH[gi] = pk(he, ho); g_woL[gi] = pk(e - he, o - ho);
    }
}

// ------------- pipelined 128x128 GEMM body -------------
#define STG_B 73728
#define PL_AH 0
#define PL_AL 18432
#define PL_BH 36864
#define PL_BL 55296

__device__ __forceinline__ void gemm_issue(const u32* aH, const u32* aL,
                                           const u32* bH, const u32* bL,
                                           u32 smb, int kb) {
    int t = threadIdx.x;
    int kp0 = kb * 32;
    u32 sbase = smb + (kb & 1) * STG_B;
    for (int i = t; i < 1024; i += 256) {
        int row = i >> 3, q = (i & 7) * 4;
        u32 d = sbase + (row * 36 + q) * 4;
        size_t so = (size_t)row * 512 + kp0 + q;
        cpa16(d + PL_AH, &aH[so]);
        cpa16(d + PL_AL, &aL[so]);
        cpa16(d + PL_BH, &bH[so]);
        cpa16(d + PL_BL, &bL[so]);
    }
    asm volatile("cp.async.commit_group;" ::: "memory");
}

__device__ __forceinline__ void gemm_body(const u32* aH, const u32* aL,
                                          const u32* bH, const u32* bL) {
    int t = threadIdx.x, w = t >> 5, lane = t & 31;
    u32 smb = smem_u32(dynsm);
    int mw = w >> 2, nw = w & 3;
    int m0w = mw * 64, n0w = nw * 32;

    int rowA = (lane & 7) + ((lane >> 3) & 1) * 8;
    int colA = ((lane >> 4) & 1) * 16;
    int rowB = (lane & 7) + ((lane >> 4) & 1) * 8;
    int colB = ((lane >> 3) & 1) * 16;

    float acc[4][4][4];
    #pragma unroll
    for (int mf = 0; mf < 4; mf++)
        #pragma unroll
        for (int nf = 0; nf < 4; nf++)
            #pragma unroll
            for (int c = 0; c < 4; c++) acc[mf][nf][c] = 0.f;

    gemm_issue(aH, aL, bH, bL, smb, 0);
    for (int kb = 0; kb < 16; kb++) {
        __syncthreads();
        if (kb < 15) {
            gemm_issue(aH, aL, bH, bL, smb, kb + 1);
            asm volatile("cp.async.wait_group 1;" ::: "memory");
        } else {
            asm volatile("cp.async.wait_group 0;" ::: "memory");
        }
        __syncthreads();

        u32 sb = smb + (kb & 1) * STG_B;
        #pragma unroll
        for (int kk = 0; kk < 4; kk++) {
            u32 aHf[4][4], aLf[4][4];
            #pragma unroll
            for (int mf = 0; mf < 4; mf++) {
                u32 adr = sb + PL_AH + (u32)(m0w + mf * 16 + rowA) * 144 + kk * 32 + colA;
                ldsm4(aHf[mf][0], aHf[mf][1], aHf[mf][2], aHf[mf][3], adr);
                ldsm4(aLf[mf][0], aLf[mf][1], aLf[mf][2], aLf[mf][3], adr + PL_AL);
            }
            u32 bHf[4][2], bLf[4][2];
            #pragma unroll
            for (int nfp = 0; nfp < 2; nfp++) {
                u32 adr = sb + PL_BH + (u32)(n0w + nfp * 16 + rowB) * 144 + kk * 32 + colB;
                ldsm4(bHf[2*nfp][0], bHf[2*nfp][1], bHf[2*nfp+1][0], bHf[2*nfp+1][1], adr);
                ldsm4(bLf[2*nfp][0], bLf[2*nfp][1], bLf[2*nfp+1][0], bLf[2*nfp+1][1],
                      adr + (PL_BL - PL_BH));
            }
            #pragma unroll
            for (int nf = 0; nf < 4; nf++)
                #pragma unroll
                for (int mf = 0; mf < 4; mf++) {
                    mma16816(acc[mf][nf], aHf[mf], bHf[nf][0], bHf[nf][1]);
                    mma16816(acc[mf][nf], aLf[mf], bHf[nf][0], bHf[nf][1]);
                    mma16816(acc[mf][nf], aHf[mf], bLf[nf][0], bLf[nf][1]);
                }
        }
    }

    __syncthreads();
    float* Cs = (float*)dynsm; const int CP = 133;
    int g = lane >> 2, r = lane & 3;
    #pragma unroll
    for (int mf = 0; mf < 4; mf++)
        #pragma unroll
        for (int nf = 0; nf < 4; nf++) {
            int row = m0w + mf * 16 + g, col = n0w + nf * 8 + 2 * r;
            Cs[row * CP + col] = acc[mf][nf][0];
            Cs[row * CP + col + 1] = acc[mf][nf][1];
            Cs[(row + 8) * CP + col] = acc[mf][nf][2];
            Cs[(row + 8) * CP + col + 1] = acc[mf][nf][3];
        }
    __syncthreads();
}

// ---------------- fused QKV GEMM ----------------
__global__ __launch_bounds__(256, 1) void qkv_gemm() {
    int brow = blockIdx.x * 128;
    int b = brow >> 11, lloc = brow & 2047;
    int mat = blockIdx.y >> 3, h0 = (blockIdx.y & 7) * 2;
    int t = threadIdx.x;

    const size_t wbase = (size_t)(mat * Hh + h0) * DKk * 512;
    gemm_body(g_xH + (size_t)brow * 512, g_xL + (size_t)brow * 512,
              g_wH + wbase, g_wL + wbase);

    float* Cs = (float*)dynsm; const int CP = 133;
    if (mat < 2) {
        u32* dH = mat ? g_KH : g_QH;
        u32* dL = mat ? g_KL : g_QL;
        for (int i = t; i < 128 * 64; i += 256) {
            int lr = i >> 6, dp = i & 63;
            int head = dp >> 5, dkp = dp & 31;
            float v0 = Cs[lr * CP + 2 * dp], v1 = Cs[lr * CP + 2 * dp + 1];
            float h1 = bhi(v0), h2 = bhi(v1);
            size_t gi = ((size_t)(b * 16 + h0 + head) * Ll + lloc + lr) * 32 + dkp;
            dH[gi] = pk(h1, h2); dL[gi] = pk(v0 - h1, v1 - h2);
        }
    } else {
        for (int i = t; i < 128 * 64; i += 256) {
            int nl = i >> 6, lp = i & 63;
            int head = nl >> 6, dk = nl & 63;
            float v0 = Cs[(2 * lp) * CP + nl], v1 = Cs[(2 * lp + 1) * CP + nl];
            float h1 = bhi(v0), h2 = bhi(v1);
            size_t gi = ((size_t)(b * 16 + h0 + head) * DKk + dk) * 1024 + (lloc >> 1) + lp;
            g_VtH[gi] = pk(h1, h2); g_VtL[gi] = pk(v0 - h1, v1 - h2);
        }
    }
}

// ---------------- output projection ----------------
__global__ __launch_bounds__(256, 1) void oproj_gemm(float* __restrict__ out) {
    int brow = blockIdx.x * 128;
    int b = brow >> 11, lloc = brow & 2047;
    int d0 = blockIdx.y * 128;
    int t = threadIdx.x;

    gemm_body(g_HdH + (size_t)brow * 512, g_HdL + (size_t)brow * 512,
              g_woH + (size_t)d0 * 512, g_woL + (size_t)d0 * 512);

    float* Cs = (float*)dynsm; const int CP = 133;
    for (int i = t; i < 128 * 128; i += 256) {
        int dc = i >> 7, lc = i & 127;
        out[((size_t)b * Dd + d0 + dc) * Ll + lloc + lc] = Cs[lc * CP + dc];
    }
}

// ---------------- flash attention: warp-private softmax + cp.async ----------------
// 8 warps x 16 rows each; all 64 keys per warp. Zero cross-warp traffic in loop.
// smem (u32): QsH[0,4608) QsL[4608,9216); stages at 9216 + s*9344:
//   KH[0,2304) KL[2304,4608) VH[4608,6912) VL[6912,9216) kms[9216,9280)
#define FST0 9216
#define FSSTR 9344
#define FLASH_U32 (9216 + 2 * 9344)

__device__ __forceinline__ void flash_issue(const u32* kH, const u32* kL,
                                            const u32* vH, const u32* vL,
                                            const float* mrow_g, u32 smb, int kb) {
    int t = threadIdx.x;
    u32 sb = smb + (FST0 + (kb & 1) * FSSTR) * 4;
    int kp0 = kb * 32;
    for (int c = t; c < 512; c += 256) {
        int row = c >> 3, q = (c & 7) * 4;
        u32 d = sb + (row * 36 + q) * 4;
        cpa16(d,            &kH[(size_t)(kb * 64 + row) * 32 + q]);
        cpa16(d + 2304 * 4, &kL[(size_t)(kb * 64 + row) * 32 + q]);
        cpa16(d + 4608 * 4, &vH[(size_t)row * 1024 + kp0 + q]);
        cpa16(d + 6912 * 4, &vL[(size_t)row * 1024 + kp0 + q]);
    }
    if (t < 16) cpa16(sb + 9216 * 4 + t * 16, &mrow_g[kb * 64 + t * 4]);
    asm volatile("cp.async.commit_group;" ::: "memory");
}

__global__ __launch_bounds__(256, 1) void flash_mma(const float* __restrict__ mask) {
    int bh = blockIdx.y, b = bh >> 4, h = bh & 15, l0 = blockIdx.x * 128;
    int t = threadIdx.x, w = t >> 5, lane = t & 31, g = lane >> 2, r = lane & 3;
    int m0w = w * 16;
    u32 smb = smem_u32(dynsm);

    int rowA = (lane & 7) + ((lane >> 3) & 1) * 8;
    int colA = ((lane >> 4) & 1) * 16;
    int rowB = (lane & 7) + ((lane >> 4) & 1) * 8;
    int colB = ((lane >> 3) & 1) * 16;

    const u32* kHp = g_KH + (size_t)bh * Ll * 32;
    const u32* kLp = g_KL + (size_t)bh * Ll * 32;
    const u32* vHp = g_VtH + (size_t)bh * DKk * 1024;
    const u32* vLp = g_VtL + (size_t)bh * DKk * 1024;
    const float* mg = mask + (size_t)b * Ll;

    flash_issue(kHp, kLp, vHp, vLp, mg, smb, 0);

    // load Q tile (pitch 36)
    const u32* qH = g_QH + ((size_t)bh * Ll + l0) * 32;
    const u32* qL = g_QL + ((size_t)bh * Ll + l0) * 32;
    for (int i = t; i < 1024; i += 256) {
        int row = i >> 3, q = (i & 7) * 4;
        *(uint4*)&dynsm[row * 36 + q]        = *(const uint4*)&qH[(size_t)row * 32 + q];
        *(uint4*)&dynsm[4608 + row * 36 + q] = *(const uint4*)&qL[(size_t)row * 32 + q];
    }

    float O[8][4];
    #pragma unroll
    for (int nf = 0; nf < 8; nf++)
        #pragma unroll
        for (int c = 0; c < 4; c++) O[nf][c] = 0.f;
    float mA = -INFINITY, mB = -INFINITY, lA = 0.f, lB = 0.f;

    for (int kb = 0; kb < 32; kb++) {
        asm volatile("cp.async.wait_group 0;" ::: "memory");
        __syncthreads();
        if (kb < 31) flash_issue(kHp, kLp, vHp, vLp, mg, smb, kb + 1);

        u32 sb = smb + (FST0 + (kb & 1) * FSSTR) * 4;
        float* kms = (float*)(dynsm + FST0 + (kb & 1) * FSSTR + 9216);

        // ---- S = Q @ K^T : 16 rows x 64 keys ----
        float sa[8][4];
        #pragma unroll
        for (int nf = 0; nf < 8; nf++)
            #pragma unroll
            for (int c = 0; c < 4; c++) sa[nf][c] = 0.f;
        #pragma unroll
        for (int kk = 0; kk < 4; kk++) {
            u32 aH[4], aL[4];
            u32 adrQ = smb + (u32)(m0w + rowA) * 144 + kk * 32 + colA;
            ldsm4(aH[0], aH[1], aH[2], aH[3], adrQ);
            ldsm4(aL[0], aL[1], aL[2], aL[3], adrQ + 4608 * 4);
            u32 bH[8][2], bL[8][2];
            #pragma unroll
            for (int nfp = 0; nfp < 4; nfp++) {
                u32 adrK = sb + (u32)(nfp * 16 + rowB) * 144 + kk * 32 + colB;
                ldsm4(bH[2*nfp][0], bH[2*nfp][1], bH[2*nfp+1][0], bH[2*nfp+1][1], adrK);
                ldsm4(bL[2*nfp][0], bL[2*nfp][1], bL[2*nfp+1][0], bL[2*nfp+1][1], adrK + 2304 * 4);
            }
            #pragma unroll
            for (int nf = 0; nf < 8; nf++) {
                mma16816(sa[nf], aH, bH[nf][0], bH[nf][1]);
                mma16816(sa[nf], aL, bH[nf][0], bH[nf][1]);
                mma16816(sa[nf], aH, bL[nf][0], bL[nf][1]);
            }
        }

        // ---- mask + warp-private online softmax (registers only) ----
        float pmA = -INFINITY, pmB = -INFINITY;
        #pragma unroll
        for (int nf = 0; nf < 8; nf++) {
            int kc = nf * 8 + 2 * r;
            bool k0 = kms[kc] > 0.5f, k1 = kms[kc + 1] > 0.5f;
            if (!k0) { sa[nf][0] = -1e30f; sa[nf][2] = -1e30f; }
            if (!k1) { sa[nf][1] = -1e30f; sa[nf][3] = -1e30f; }
            pmA = fmaxf(pmA, fmaxf(sa[nf][0], sa[nf][1]));
            pmB = fmaxf(pmB, fmaxf(sa[nf][2], sa[nf][3]));
        }
        pmA = fmaxf(pmA, __shfl_xor_sync(0xffffffffu, pmA, 1));
        pmA = fmaxf(pmA, __shfl_xor_sync(0xffffffffu, pmA, 2));
        pmB = fmaxf(pmB, __shfl_xor_sync(0xffffffffu, pmB, 1));
        pmB = fmaxf(pmB, __shfl_xor_sync(0xffffffffu, pmB, 2));
        float mnA = fmaxf(mA, pmA), mnB = fmaxf(mB, pmB);
        float alA = __expf(mA - mnA), alB = __expf(mB - mnB);
        float psA = 0.f, psB = 0.f;
        #pragma unroll
        for (int nf = 0; nf < 8; nf++) {
            float e0 = __expf(sa[nf][0] - mnA), e1 = __expf(sa[nf][1] - mnA);
            float e2 = __expf(sa[nf][2] - mnB), e3 = __expf(sa[nf][3] - mnB);
            sa[nf][0] = e0; sa[nf][1] = e1; sa[nf][2] = e2; sa[nf][3] = e3;
            psA += e0 + e1; psB += e2 + e3;
        }
        psA += __shfl_xor_sync(0xffffffffu, psA, 1);
        psA += __shfl_xor_sync(0xffffffffu, psA, 2);
        psB += __shfl_xor_sync(0xffffffffu, psB, 1);
        psB += __shfl_xor_sync(0xffffffffu, psB, 2);
        lA = lA * alA + psA; lB = lB * alB + psB;
        mA = mnA; mB = mnB;
        #pragma unroll
        for (int nf = 0; nf < 8; nf++) {
            O[nf][0] *= alA; O[nf][1] *= alA;
            O[nf][2] *= alB; O[nf][3] *= alB;
        }

        // ---- O += P @ V ----
        #pragma unroll
        for (int kp = 0; kp < 4; kp++) {
            float e00 = sa[2*kp][0],   e01 = sa[2*kp][1],   e02 = sa[2*kp][2],   e03 = sa[2*kp][3];
            float e10 = sa[2*kp+1][0], e11 = sa[2*kp+1][1], e12 = sa[2*kp+1][2], e13 = sa[2*kp+1][3];
            float h00 = bhi(e00), h01 = bhi(e01), h02 = bhi(e02), h03 = bhi(e03);
            float h10 = bhi(e10), h11 = bhi(e11), h12 = bhi(e12), h13 = bhi(e13);
            u32 pHf[4] = { pk(h00, h01), pk(h02, h03), pk(h10, h11), pk(h12, h13) };
            u32 pLf[4] = { pk(e00 - h00, e01 - h01), pk(e02 - h02, e03 - h03),
                           pk(e10 - h10, e11 - h11), pk(e12 - h12, e13 - h13) };
            u32 bH[8][2], bL[8][2];
            #pragma unroll
            for (int nfp = 0; nfp < 4; nfp++) {
                u32 adrV = sb + 4608 * 4 + (u32)(nfp * 16 + rowB) * 144 + kp * 32 + colB;
                ldsm4(bH[2*nfp][0], bH[2*nfp][1], bH[2*nfp+1][0], bH[2*nfp+1][1], adrV);
                ldsm4(bL[2*nfp][0], bL[2*nfp][1], bL[2*nfp+1][0], bL[2*nfp+1][1], adrV + 2304 * 4);
            }
            #pragma unroll
            for (int nf = 0; nf < 8; nf++) {
                mma16816(O[nf], pHf, bH[nf][0], bH[nf][1]);
                mma16816(O[nf], pLf, bH[nf][0], bH[nf][1]);
                mma16816(O[nf], pHf, bL[nf][0], bL[nf][1]);
            }
        }
    }

    // ---- epilogue: normalize, query mask, write packed Hd (warp-private rows) ----
    int row = m0w + g;
    float s0 = mg[l0 + row] / lA;
    float s1 = mg[l0 + row + 8] / lB;
    #pragma unroll
    for (int nf = 0; nf < 8; nf++) {
        float c0 = O[nf][0] * s0, c1 = O[nf][1] * s0;
        float c2 = O[nf][2] * s1, c3 = O[nf][3] * s1;
        size_t gi = ((size_t)b * Ll + l0 + row) * 512 + h * 32 + nf * 4 + r;
        float h0 = bhi(c0), h1 = bhi(c1);
        g_HdH[gi] = pk(h0, h1); g_HdL[gi] = pk(c0 - h0, c1 - h1);
        float h2 = bhi(c2), h3 = bhi(c3);
        g_HdH[gi + 8 * 512] = pk(h2, h3);
        g_HdL[gi + 8 * 512] = pk(c2 - h2, c3 - h3);
    }
}

// ---------------------------------------------------------------------------
extern "C" void kernel_launch(void* const* d_in, const int* in_sizes, int n_in,
                              void* d_out, int out_size) {
    const float* x    = (const float*)d_in[0];
    const float* mask = (const float*)d_in[1];
    const float* Wq   = (const float*)d_in[2];
    const float* Wk   = (const float*)d_in[3];
    const float* Wv   = (const float*)d_in[4];
    const float* Wo   = (const float*)d_in[5];
    float* out = (float*)d_out;

    const int GEMM_SMEM  = 2 * STG_B;        // 147456 B
    const int FLASH_SMEM = FLASH_U32 * 4;    // 111616 B
    cudaFuncSetAttribute(qkv_gemm,  cudaFuncAttributeMaxDynamicSharedMemorySize, GEMM_SMEM);
    cudaFuncSetAttribute(oproj_gemm, cudaFuncAttributeMaxDynamicSharedMemorySize, GEMM_SMEM);
    cudaFuncSetAttribute(flash_mma, cudaFuncAttributeMaxDynamicSharedMemorySize, FLASH_SMEM);

    x_split<<<dim3(Ll / 64, Dd / 64, Bz), 256>>>(x);
    w_split_t<<<dim3(Dd / 64, Hh, 3), 256>>>(Wq, Wk, Wv);
    wo_split_t<<<dim3(Dd / 64, Dd / 64), 256>>>(Wo);
    qkv_gemm<<<dim3(32, 24), 256, GEMM_SMEM>>>();
    flash_mma<<<dim3(Ll / 128, BH), 256, FLASH_SMEM>>>(mask);
    oproj_gemm<<<dim3(32, 8), 256, GEMM_SMEM>>>(out);
}

// round 14
// speedup vs baseline: 4.4820x; 1.0508x over previous
#include <cuda_runtime.h>
#include <cuda_bf16.h>
#include <math.h>
#include <stdint.h>

#define Bz 2
#define Dd 1024
#define Ll 2048
#define Hh 16
#define DKk 64
#define BH 32
typedef uint32_t u32;

// A-side activations: [b*l][dpair] hi/lo
__device__ u32 g_xH[(size_t)Bz*Ll*512],  g_xL[(size_t)Bz*Ll*512];
// QKV weights transposed: [mat][h][dk][dpair]
__device__ u32 g_wH[(size_t)3*Hh*DKk*512], g_wL[(size_t)3*Hh*DKk*512];
// Wo transposed: [d][epair]
__device__ u32 g_woH[(size_t)Dd*512],    g_woL[(size_t)Dd*512];
// Q,K: [bh][l][dkpair]
__device__ u32 g_QH[(size_t)BH*Ll*32],   g_QL[(size_t)BH*Ll*32];
__device__ u32 g_KH[(size_t)BH*Ll*32],   g_KL[(size_t)BH*Ll*32];
// V transposed: [bh][dk][lpair]
__device__ u32 g_VtH[(size_t)BH*DKk*1024], g_VtL[(size_t)BH*DKk*1024];
// heads: [b*l][epair]
__device__ u32 g_HdH[(size_t)Bz*Ll*512], g_HdL[(size_t)Bz*Ll*512];

extern __shared__ u32 dynsm[];

__device__ __forceinline__ u32 pk(float e, float o) {
    u32 d; asm("cvt.rn.bf16x2.f32 %0, %1, %2;" : "=r"(d) : "f"(o), "f"(e)); return d;
}
__device__ __forceinline__ float bhi(float x) { return __bfloat162float(__float2bfloat16_rn(x)); }
__device__ __forceinline__ void mma16816(float* c, const u32* a, u32 b0, u32 b1) {
    asm("mma.sync.aligned.m16n8k16.row.col.f32.bf16.bf16.f32 "
        "{%0,%1,%2,%3},{%4,%5,%6,%7},{%8,%9},{%0,%1,%2,%3};"
        : "+f"(c[0]), "+f"(c[1]), "+f"(c[2]), "+f"(c[3])
        : "r"(a[0]), "r"(a[1]), "r"(a[2]), "r"(a[3]), "r"(b0), "r"(b1));
}
__device__ __forceinline__ u32 smem_u32(const void* p) {
    u32 a;
    asm("{ .reg .u64 t; cvta.to.shared.u64 t, %1; cvt.u32.u64 %0, t; }" : "=r"(a) : "l"(p));
    return a;
}
__device__ __forceinline__ void ldsm4(u32& r0, u32& r1, u32& r2, u32& r3, u32 addr) {
    asm volatile("ldmatrix.sync.aligned.m8n8.x4.shared.b16 {%0,%1,%2,%3}, [%4];"
                 : "=r"(r0), "=r"(r1), "=r"(r2), "=r"(r3) : "r"(addr));
}
__device__ __forceinline__ void cpa16(u32 dst, const void* src) {
    asm volatile("cp.async.cg.shared.global [%0], [%1], 16;" :: "r"(dst), "l"(src));
}

// ---------------- prep kernels ----------------
__global__ __launch_bounds__(256) void x_split(const float* __restrict__ x) {
    __shared__ float st[64][65];
    int b = blockIdx.z, d0 = blockIdx.y * 64, l0 = blockIdx.x * 64, t = threadIdx.x;
    for (int i = t; i < 64 * 64; i += 256) {
        int dr = i >> 6, lc = i & 63;
        st[dr][lc] = x[((size_t)b * Dd + d0 + dr) * Ll + l0 + lc];
    }
    __syncthreads();
    for (int j = t; j < 64 * 32; j += 256) {
        int l = j >> 5, dp = j & 31;
        float e = st[2 * dp][l], o = st[2 * dp + 1][l];
        float he = bhi(e), ho = bhi(o);
        size_t gi = ((size_t)b * Ll + l0 + l) * 512 + (d0 >> 1) + dp;
        g_xH[gi] = pk(he, ho); g_xL[gi] = pk(e - he, o - ho);
    }
}
__global__ __launch_bounds__(256) void w_split_t(const float* __restrict__ Wq,
                                                 const float* __restrict__ Wk,
                                                 const float* __restrict__ Wv) {
    __shared__ float st[64][65];
    int mat = blockIdx.z, h = blockIdx.y, d0 = blockIdx.x * 64, t = threadIdx.x;
    const float* W = mat == 0 ? Wq : (mat == 1 ? Wk : Wv);
    float s = (mat == 0) ? 0.125f : 1.0f;
    for (int i = t; i < 64 * 64; i += 256) {
        int dr = i >> 6, kc = i & 63;
        st[dr][kc] = W[((size_t)h * Dd + d0 + dr) * DKk + kc] * s;
    }
    __syncthreads();
    for (int j = t; j < 64 * 32; j += 256) {
        int k = j >> 5, dp = j & 31;
        float e = st[2 * dp][k], o = st[2 * dp + 1][k];
        float he = bhi(e), ho = bhi(o);
        size_t gi = ((size_t)(mat * Hh + h) * DKk + k) * 512 + (d0 >> 1) + dp;
        g_wH[gi] = pk(he, ho); g_wL[gi] = pk(e - he, o - ho);
    }
}
__global__ __launch_bounds__(256) void wo_split_t(const float* __restrict__ Wo) {
    __shared__ float st[64][65];
    int e0 = blockIdx.y * 64, d0 = blockIdx.x * 64, t = threadIdx.x;
    for (int i = t; i < 64 * 64; i += 256) {
        int er = i >> 6, dc = i & 63;
        st[er][dc] = Wo[((size_t)(e0 + er)) * Dd + d0 + dc];
    }
    __syncthreads();
    for (int j = t; j < 64 * 32; j += 256) {
        int d = j >> 5, ep = j & 31;
        float e = st[2 * ep][d], o = st[2 * ep + 1][d];
        float he = bhi(e), ho = bhi(o);
        size_t gi = ((size_t)(d0 + d)) * 512 + (e0 >> 1) + ep;
        g_woH[gi] = pk(he, ho); g_woL[gi] = pk(e - he, o - ho);
    }
}

// ------------- pipelined 128x128 GEMM body (3-stage, 1 sync/k-block) -------------
#define STG_B 73728
#define NSTG 3
#define PL_AH 0
#define PL_AL 18432
#define PL_BH 36864
#define PL_BL 55296

__device__ __forceinline__ void gemm_issue(const u32* aH, const u32* aL,
                                           const u32* bH, const u32* bL,
                                           u32 smb, int kb) {
    int t = threadIdx.x;
    int kp0 = kb * 32;
    u32 sbase = smb + (kb % NSTG) * STG_B;
    for (int i = t; i < 1024; i += 256) {
        int row = i >> 3, q = (i & 7) * 4;
        u32 d = sbase + (row * 36 + q) * 4;
        size_t so = (size_t)row * 512 + kp0 + q;
        cpa16(d + PL_AH, &aH[so]);
        cpa16(d + PL_AL, &aL[so]);
        cpa16(d + PL_BH, &bH[so]);
        cpa16(d + PL_BL, &bL[so]);
    }
    asm volatile("cp.async.commit_group;" ::: "memory");
}

__device__ __forceinline__ void gemm_body(const u32* aH, const u32* aL,
                                          const u32* bH, const u32* bL) {
    int t = threadIdx.x, w = t >> 5, lane = t & 31;
    u32 smb = smem_u32(dynsm);
    int mw = w >> 2, nw = w & 3;
    int m0w = mw * 64, n0w = nw * 32;

    int rowA = (lane & 7) + ((lane >> 3) & 1) * 8;
    int colA = ((lane >> 4) & 1) * 16;
    int rowB = (lane & 7) + ((lane >> 4) & 1) * 8;
    int colB = ((lane >> 3) & 1) * 16;

    float acc[4][4][4];
    #pragma unroll
    for (int mf = 0; mf < 4; mf++)
        #pragma unroll
        for (int nf = 0; nf < 4; nf++)
            #pragma unroll
            for (int c = 0; c < 4; c++) acc[mf][nf][c] = 0.f;

    gemm_issue(aH, aL, bH, bL, smb, 0);
    gemm_issue(aH, aL, bH, bL, smb, 1);
    for (int kb = 0; kb < 16; kb++) {
        asm volatile("cp.async.wait_group 1;" ::: "memory");
        __syncthreads();
        if (kb < 14) gemm_issue(aH, aL, bH, bL, smb, kb + 2);

        u32 sb = smb + (kb % NSTG) * STG_B;
        #pragma unroll
        for (int kk = 0; kk < 4; kk++) {
            u32 aHf[4][4], aLf[4][4];
            #pragma unroll
            for (int mf = 0; mf < 4; mf++) {
                u32 adr = sb + PL_AH + (u32)(m0w + mf * 16 + rowA) * 144 + kk * 32 + colA;
                ldsm4(aHf[mf][0], aHf[mf][1], aHf[mf][2], aHf[mf][3], adr);
                ldsm4(aLf[mf][0], aLf[mf][1], aLf[mf][2], aLf[mf][3], adr + PL_AL);
            }
            u32 bHf[4][2], bLf[4][2];
            #pragma unroll
            for (int nfp = 0; nfp < 2; nfp++) {
                u32 adr = sb + PL_BH + (u32)(n0w + nfp * 16 + rowB) * 144 + kk * 32 + colB;
                ldsm4(bHf[2*nfp][0], bHf[2*nfp][1], bHf[2*nfp+1][0], bHf[2*nfp+1][1], adr);
                ldsm4(bLf[2*nfp][0], bLf[2*nfp][1], bLf[2*nfp+1][0], bLf[2*nfp+1][1],
                      adr + (PL_BL - PL_BH));
            }
            #pragma unroll
            for (int nf = 0; nf < 4; nf++)
                #pragma unroll
                for (int mf = 0; mf < 4; mf++) {
                    mma16816(acc[mf][nf], aHf[mf], bHf[nf][0], bHf[nf][1]);
                    mma16816(acc[mf][nf], aLf[mf], bHf[nf][0], bHf[nf][1]);
                    mma16816(acc[mf][nf], aHf[mf], bLf[nf][0], bLf[nf][1]);
                }
        }
    }

    __syncthreads();
    float* Cs = (float*)dynsm; const int CP = 133;
    int g = lane >> 2, r = lane & 3;
    #pragma unroll
    for (int mf = 0; mf < 4; mf++)
        #pragma unroll
        for (int nf = 0; nf < 4; nf++) {
            int row = m0w + mf * 16 + g, col = n0w + nf * 8 + 2 * r;
            Cs[row * CP + col] = acc[mf][nf][0];
            Cs[row * CP + col + 1] = acc[mf][nf][1];
            Cs[(row + 8) * CP + col] = acc[mf][nf][2];
            Cs[(row + 8) * CP + col + 1] = acc[mf][nf][3];
        }
    __syncthreads();
}

// ---------------- fused QKV GEMM ----------------
__global__ __launch_bounds__(256, 1) void qkv_gemm() {
    int brow = blockIdx.x * 128;
    int b = brow >> 11, lloc = brow & 2047;
    int mat = blockIdx.y >> 3, h0 = (blockIdx.y & 7) * 2;
    int t = threadIdx.x;

    const size_t wbase = (size_t)(mat * Hh + h0) * DKk * 512;
    gemm_body(g_xH + (size_t)brow * 512, g_xL + (size_t)brow * 512,
              g_wH + wbase, g_wL + wbase);

    float* Cs = (float*)dynsm; const int CP = 133;
    if (mat < 2) {
        u32* dH = mat ? g_KH : g_QH;
        u32* dL = mat ? g_KL : g_QL;
        for (int i = t; i < 128 * 64; i += 256) {
            int lr = i >> 6, dp = i & 63;
            int head = dp >> 5, dkp = dp & 31;
            float v0 = Cs[lr * CP + 2 * dp], v1 = Cs[lr * CP + 2 * dp + 1];
            float h1 = bhi(v0), h2 = bhi(v1);
            size_t gi = ((size_t)(b * 16 + h0 + head) * Ll + lloc + lr) * 32 + dkp;
            dH[gi] = pk(h1, h2); dL[gi] = pk(v0 - h1, v1 - h2);
        }
    } else {
        for (int i = t; i < 128 * 64; i += 256) {
            int nl = i >> 6, lp = i & 63;
            int head = nl >> 6, dk = nl & 63;
            float v0 = Cs[(2 * lp) * CP + nl], v1 = Cs[(2 * lp + 1) * CP + nl];
            float h1 = bhi(v0), h2 = bhi(v1);
            size_t gi = ((size_t)(b * 16 + h0 + head) * DKk + dk) * 1024 + (lloc >> 1) + lp;
            g_VtH[gi] = pk(h1, h2); g_VtL[gi] = pk(v0 - h1, v1 - h2);
        }
    }
}

// ---------------- output projection ----------------
__global__ __launch_bounds__(256, 1) void oproj_gemm(float* __restrict__ out) {
    int brow = blockIdx.x * 128;
    int b = brow >> 11, lloc = brow & 2047;
    int d0 = blockIdx.y * 128;
    int t = threadIdx.x;

    gemm_body(g_HdH + (size_t)brow * 512, g_HdL + (size_t)brow * 512,
              g_woH + (size_t)d0 * 512, g_woL + (size_t)d0 * 512);

    float* Cs = (float*)dynsm; const int CP = 133;
    for (int i = t; i < 128 * 128; i += 256) {
        int dc = i >> 7, lc = i & 127;
        out[((size_t)b * Dd + d0 + dc) * Ll + lloc + lc] = Cs[lc * CP + dc];
    }
}

// ---------------- flash attention: warp-private softmax + cp.async ----------------
// 8 warps x 16 rows each; all 64 keys per warp. 2 CTAs/SM via launch_bounds.
#define FST0 9216
#define FSSTR 9344
#define FLASH_U32 (9216 + 2 * 9344)

__device__ __forceinline__ void flash_issue(const u32* kH, const u32* kL,
                                            const u32* vH, const u32* vL,
                                            const float* mrow_g, u32 smb, int kb) {
    int t = threadIdx.x;
    u32 sb = smb + (FST0 + (kb & 1) * FSSTR) * 4;
    int kp0 = kb * 32;
    for (int c = t; c < 512; c += 256) {
        int row = c >> 3, q = (c & 7) * 4;
        u32 d = sb + (row * 36 + q) * 4;
        cpa16(d,            &kH[(size_t)(kb * 64 + row) * 32 + q]);
        cpa16(d + 2304 * 4, &kL[(size_t)(kb * 64 + row) * 32 + q]);
        cpa16(d + 4608 * 4, &vH[(size_t)row * 1024 + kp0 + q]);
        cpa16(d + 6912 * 4, &vL[(size_t)row * 1024 + kp0 + q]);
    }
    if (t < 16) cpa16(sb + 9216 * 4 + t * 16, &mrow_g[kb * 64 + t * 4]);
    asm volatile("cp.async.commit_group;" ::: "memory");
}

__global__ __launch_bounds__(256, 2) void flash_mma(const float* __restrict__ mask) {
    int bh = blockIdx.y, b = bh >> 4, h = bh & 15, l0 = blockIdx.x * 128;
    int t = threadIdx.x, w = t >> 5, lane = t & 31, g = lane >> 2, r = lane & 3;
    int m0w = w * 16;
    u32 smb = smem_u32(dynsm);

    int rowA = (lane & 7) + ((lane >> 3) & 1) * 8;
    int colA = ((lane >> 4) & 1) * 16;
    int rowB = (lane & 7) + ((lane >> 4) & 1) * 8;
    int colB = ((lane >> 3) & 1) * 16;

    const u32* kHp = g_KH + (size_t)bh * Ll * 32;
    const u32* kLp = g_KL + (size_t)bh * Ll * 32;
    const u32* vHp = g_VtH + (size_t)bh * DKk * 1024;
    const u32* vLp = g_VtL + (size_t)bh * DKk * 1024;
    const float* mg = mask + (size_t)b * Ll;

    flash_issue(kHp, kLp, vHp, vLp, mg, smb, 0);

    const u32* qH = g_QH + ((size_t)bh * Ll + l0) * 32;
    const u32* qL = g_QL + ((size_t)bh * Ll + l0) * 32;
    for (int i = t; i < 1024; i += 256) {
        int row = i >> 3, q = (i & 7) * 4;
        *(uint4*)&dynsm[row * 36 + q]        = *(const uint4*)&qH[(size_t)row * 32 + q];
        *(uint4*)&dynsm[4608 + row * 36 + q] = *(const uint4*)&qL[(size_t)row * 32 + q];
    }

    float O[8][4];
    #pragma unroll
    for (int nf = 0; nf < 8; nf++)
        #pragma unroll
        for (int c = 0; c < 4; c++) O[nf][c] = 0.f;
    float mA = -INFINITY, mB = -INFINITY, lA = 0.f, lB = 0.f;

    for (int kb = 0; kb < 32; kb++) {
        asm volatile("cp.async.wait_group 0;" ::: "memory");
        __syncthreads();
        if (kb < 31) flash_issue(kHp, kLp, vHp, vLp, mg, smb, kb + 1);

        u32 sb = smb + (FST0 + (kb & 1) * FSSTR) * 4;
        float* kms = (float*)(dynsm + FST0 + (kb & 1) * FSSTR + 9216);

        float sa[8][4];
        #pragma unroll
        for (int nf = 0; nf < 8; nf++)
            #pragma unroll
            for (int c = 0; c < 4; c++) sa[nf][c] = 0.f;
        #pragma unroll
        for (int kk = 0; kk < 4; kk++) {
            u32 aH[4], aL[4];
            u32 adrQ = smb + (u32)(m0w + rowA) * 144 + kk * 32 + colA;
            ldsm4(aH[0], aH[1], aH[2], aH[3], adrQ);
            ldsm4(aL[0], aL[1], aL[2], aL[3], adrQ + 4608 * 4);
            u32 bH[8][2], bL[8][2];
            #pragma unroll
            for (int nfp = 0; nfp < 4; nfp++) {
                u32 adrK = sb + (u32)(nfp * 16 + rowB) * 144 + kk * 32 + colB;
                ldsm4(bH[2*nfp][0], bH[2*nfp][1], bH[2*nfp+1][0], bH[2*nfp+1][1], adrK);
                ldsm4(bL[2*nfp][0], bL[2*nfp][1], bL[2*nfp+1][0], bL[2*nfp+1][1], adrK + 2304 * 4);
            }
            #pragma unroll
            for (int nf = 0; nf < 8; nf++) {
                mma16816(sa[nf], aH, bH[nf][0], bH[nf][1]);
                mma16816(sa[nf], aL, bH[nf][0], bH[nf][1]);
                mma16816(sa[nf], aH, bL[nf][0], bL[nf][1]);
            }
        }

        float pmA = -INFINITY, pmB = -INFINITY;
        #pragma unroll
        for (int nf = 0; nf < 8; nf++) {
            int kc = nf * 8 + 2 * r;
            bool k0 = kms[kc] > 0.5f, k1 = kms[kc + 1] > 0.5f;
            if (!k0) { sa[nf][0] = -1e30f; sa[nf][2] = -1e30f; }
            if (!k1) { sa[nf][1] = -1e30f; sa[nf][3] = -1e30f; }
            pmA = fmaxf(pmA, fmaxf(sa[nf][0], sa[nf][1]));
            pmB = fmaxf(pmB, fmaxf(sa[nf][2], sa[nf][3]));
        }
        pmA = fmaxf(pmA, __shfl_xor_sync(0xffffffffu, pmA, 1));
        pmA = fmaxf(pmA, __shfl_xor_sync(0xffffffffu, pmA, 2));
        pmB = fmaxf(pmB, __shfl_xor_sync(0xffffffffu, pmB, 1));
        pmB = fmaxf(pmB, __shfl_xor_sync(0xffffffffu, pmB, 2));
        float mnA = fmaxf(mA, pmA), mnB = fmaxf(mB, pmB);
        float alA = __expf(mA - mnA), alB = __expf(mB - mnB);
        float psA = 0.f, psB = 0.f;
        #pragma unroll
        for (int nf = 0; nf < 8; nf++) {
            float e0 = __expf(sa[nf][0] - mnA), e1 = __expf(sa[nf][1] - mnA);
            float e2 = __expf(sa[nf][2] - mnB), e3 = __expf(sa[nf][3] - mnB);
            sa[nf][0] = e0; sa[nf][1] = e1; sa[nf][2] = e2; sa[nf][3] = e3;
            psA += e0 + e1; psB += e2 + e3;
        }
        psA += __shfl_xor_sync(0xffffffffu, psA, 1);
        psA += __shfl_xor_sync(0xffffffffu, psA, 2);
        psB += __shfl_xor_sync(0xffffffffu, psB, 1);
        psB += __shfl_xor_sync(0xffffffffu, psB, 2);
        lA = lA * alA + psA; lB = lB * alB + psB;
        mA = mnA; mB = mnB;
        #pragma unroll
        for (int nf = 0; nf < 8; nf++) {
            O[nf][0] *= alA; O[nf][1] *= alA;
            O[nf][2] *= alB; O[nf][3] *= alB;
        }

        #pragma unroll
        for (int kp = 0; kp < 4; kp++) {
            float e00 = sa[2*kp][0],   e01 = sa[2*kp][1],   e02 = sa[2*kp][2],   e03 = sa[2*kp][3];
            float e10 = sa[2*kp+1][0], e11 = sa[2*kp+1][1], e12 = sa[2*kp+1][2], e13 = sa[2*kp+1][3];
            float h00 = bhi(e00), h01 = bhi(e01), h02 = bhi(e02), h03 = bhi(e03);
            float h10 = bhi(e10), h11 = bhi(e11), h12 = bhi(e12), h13 = bhi(e13);
            u32 pHf[4] = { pk(h00, h01), pk(h02, h03), pk(h10, h11), pk(h12, h13) };
            u32 pLf[4] = { pk(e00 - h00, e01 - h01), pk(e02 - h02, e03 - h03),
                           pk(e10 - h10, e11 - h11), pk(e12 - h12, e13 - h13) };
            u32 bH[8][2], bL[8][2];
            #pragma unroll
            for (int nfp = 0; nfp < 4; nfp++) {
                u32 adrV = sb + 4608 * 4 + (u32)(nfp * 16 + rowB) * 144 + kp * 32 + colB;
                ldsm4(bH[2*nfp][0], bH[2*nfp][1], bH[2*nfp+1][0], bH[2*nfp+1][1], adrV);
                ldsm4(bL[2*nfp][0], bL[2*nfp][1], bL[2*nfp+1][0], bL[2*nfp+1][1], adrV + 2304 * 4);
            }
            #pragma unroll
            for (int nf = 0; nf < 8; nf++) {
                mma16816(O[nf], pHf, bH[nf][0], bH[nf][1]);
                mma16816(O[nf], pLf, bH[nf][0], bH[nf][1]);
                mma16816(O[nf], pHf, bL[nf][0], bL[nf][1]);
            }
        }
    }

    int row = m0w + g;
    float s0 = mg[l0 + row] / lA;
    float s1 = mg[l0 + row + 8] / lB;
    #pragma unroll
    for (int nf = 0; nf < 8; nf++) {
        float c0 = O[nf][0] * s0, c1 = O[nf][1] * s0;
        float c2 = O[nf][2] * s1, c3 = O[nf][3] * s1;
        size_t gi = ((size_t)b * Ll + l0 + row) * 512 + h * 32 + nf * 4 + r;
        float h0 = bhi(c0), h1 = bhi(c1);
        g_HdH[gi] = pk(h0, h1); g_HdL[gi] = pk(c0 - h0, c1 - h1);
        float h2 = bhi(c2), h3 = bhi(c3);
        g_HdH[gi + 8 * 512] = pk(h2, h3);
        g_HdL[gi + 8 * 512] = pk(c2 - h2, c3 - h3);
    }
}

// ---------------------------------------------------------------------------
extern "C" void kernel_launch(void* const* d_in, const int* in_sizes, int n_in,
                              void* d_out, int out_size) {
    const float* x    = (const float*)d_in[0];
    const float* mask = (const float*)d_in[1];
    const float* Wq   = (const float*)d_in[2];
    const float* Wk   = (const float*)d_in[3];
    const float* Wv   = (const float*)d_in[4];
    const float* Wo   = (const float*)d_in[5];
    float* out = (float*)d_out;

    const int GEMM_SMEM  = NSTG * STG_B;     // 221184 B
    const int FLASH_SMEM = FLASH_U32 * 4;    // 111616 B
    cudaFuncSetAttribute(qkv_gemm,  cudaFuncAttributeMaxDynamicSharedMemorySize, GEMM_SMEM);
    cudaFuncSetAttribute(oproj_gemm, cudaFuncAttributeMaxDynamicSharedMemorySize, GEMM_SMEM);
    cudaFuncSetAttribute(flash_mma, cudaFuncAttributeMaxDynamicSharedMemorySize, FLASH_SMEM);

    x_split<<<dim3(Ll / 64, Dd / 64, Bz), 256>>>(x);
    w_split_t<<<dim3(Dd / 64, Hh, 3), 256>>>(Wq, Wk, Wv);
    wo_split_t<<<dim3(Dd / 64, Dd / 64), 256>>>(Wo);
    qkv_gemm<<<dim3(32, 24), 256, GEMM_SMEM>>>();
    flash_mma<<<dim3(Ll / 128, BH), 256, FLASH_SMEM>>>(mask);
    oproj_gemm<<<dim3(32, 8), 256, GEMM_SMEM>>>(out);
}

// round 15
// speedup vs baseline: 4.5919x; 1.0245x over previous
#include <cuda_runtime.h>
#include <cuda_bf16.h>
#include <math.h>
#include <stdint.h>

#define Bz 2
#define Dd 1024
#define Ll 2048
#define Hh 16
#define DKk 64
#define BH 32
typedef uint32_t u32;

// A-side activations: [b*l][dpair] hi/lo
__device__ u32 g_xH[(size_t)Bz*Ll*512],  g_xL[(size_t)Bz*Ll*512];
// QKV weights transposed: [mat][h][dk][dpair]
__device__ u32 g_wH[(size_t)3*Hh*DKk*512], g_wL[(size_t)3*Hh*DKk*512];
// Wo transposed: [d][epair]
__device__ u32 g_woH[(size_t)Dd*512],    g_woL[(size_t)Dd*512];
// Q,K: [bh][l][dkpair]
__device__ u32 g_QH[(size_t)BH*Ll*32],   g_QL[(size_t)BH*Ll*32];
__device__ u32 g_KH[(size_t)BH*Ll*32],   g_KL[(size_t)BH*Ll*32];
// V transposed: [bh][dk][lpair]
__device__ u32 g_VtH[(size_t)BH*DKk*1024], g_VtL[(size_t)BH*DKk*1024];
// heads: [b*l][epair]
__device__ u32 g_HdH[(size_t)Bz*Ll*512], g_HdL[(size_t)Bz*Ll*512];

extern __shared__ u32 dynsm[];

__device__ __forceinline__ u32 pk(float e, float o) {
    u32 d; asm("cvt.rn.bf16x2.f32 %0, %1, %2;" : "=r"(d) : "f"(o), "f"(e)); return d;
}
__device__ __forceinline__ float bhi(float x) { return __bfloat162float(__float2bfloat16_rn(x)); }
__device__ __forceinline__ void mma16816(float* c, const u32* a, u32 b0, u32 b1) {
    asm("mma.sync.aligned.m16n8k16.row.col.f32.bf16.bf16.f32 "
        "{%0,%1,%2,%3},{%4,%5,%6,%7},{%8,%9},{%0,%1,%2,%3};"
        : "+f"(c[0]), "+f"(c[1]), "+f"(c[2]), "+f"(c[3])
        : "r"(a[0]), "r"(a[1]), "r"(a[2]), "r"(a[3]), "r"(b0), "r"(b1));
}
__device__ __forceinline__ u32 smem_u32(const void* p) {
    u32 a;
    asm("{ .reg .u64 t; cvta.to.shared.u64 t, %1; cvt.u32.u64 %0, t; }" : "=r"(a) : "l"(p));
    return a;
}
__device__ __forceinline__ void ldsm4(u32& r0, u32& r1, u32& r2, u32& r3, u32 addr) {
    asm volatile("ldmatrix.sync.aligned.m8n8.x4.shared.b16 {%0,%1,%2,%3}, [%4];"
                 : "=r"(r0), "=r"(r1), "=r"(r2), "=r"(r3) : "r"(addr));
}
__device__ __forceinline__ void cpa16(u32 dst, const void* src) {
    asm volatile("cp.async.cg.shared.global [%0], [%1], 16;" :: "r"(dst), "l"(src));
}

// ---------------- prep kernels ----------------
__global__ __launch_bounds__(256) void x_split(const float* __restrict__ x) {
    __shared__ float st[64][65];
    int b = blockIdx.z, d0 = blockIdx.y * 64, l0 = blockIdx.x * 64, t = threadIdx.x;
    for (int i = t; i < 64 * 64; i += 256) {
        int dr = i >> 6, lc = i & 63;
        st[dr][lc] = x[((size_t)b * Dd + d0 + dr) * Ll + l0 + lc];
    }
    __syncthreads();
    for (int j = t; j < 64 * 32; j += 256) {
        int l = j >> 5, dp = j & 31;
        float e = st[2 * dp][l], o = st[2 * dp + 1][l];
        float he = bhi(e), ho = bhi(o);
        size_t gi = ((size_t)b * Ll + l0 + l) * 512 + (d0 >> 1) + dp;
        g_xH[gi] = pk(he, ho); g_xL[gi] = pk(e - he, o - ho);
    }
}
__global__ __launch_bounds__(256) void w_split_t(const float* __restrict__ Wq,
                                                 const float* __restrict__ Wk,
                                                 const float* __restrict__ Wv) {
    __shared__ float st[64][65];
    int mat = blockIdx.z, h = blockIdx.y, d0 = blockIdx.x * 64, t = threadIdx.x;
    const float* W = mat == 0 ? Wq : (mat == 1 ? Wk : Wv);
    float s = (mat == 0) ? 0.125f : 1.0f;
    for (int i = t; i < 64 * 64; i += 256) {
        int dr = i >> 6, kc = i & 63;
        st[dr][kc] = W[((size_t)h * Dd + d0 + dr) * DKk + kc] * s;
    }
    __syncthreads();
    for (int j = t; j < 64 * 32; j += 256) {
        int k = j >> 5, dp = j & 31;
        float e = st[2 * dp][k], o = st[2 * dp + 1][k];
        float he = bhi(e), ho = bhi(o);
        size_t gi = ((size_t)(mat * Hh + h) * DKk + k) * 512 + (d0 >> 1) + dp;
        g_wH[gi] = pk(he, ho); g_wL[gi] = pk(e - he, o - ho);
    }
}
__global__ __launch_bounds__(256) void wo_split_t(const float* __restrict__ Wo) {
    __shared__ float st[64][65];
    int e0 = blockIdx.y * 64, d0 = blockIdx.x * 64, t = threadIdx.x;
    for (int i = t; i < 64 * 64; i += 256) {
        int er = i >> 6, dc = i & 63;
        st[er][dc] = Wo[((size_t)(e0 + er)) * Dd + d0 + dc];
    }
    __syncthreads();
    for (int j = t; j < 64 * 32; j += 256) {
        int d = j >> 5, ep = j & 31;
        float e = st[2 * ep][d], o = st[2 * ep + 1][d];
        float he = bhi(e), ho = bhi(o);
        size_t gi = ((size_t)(d0 + d)) * 512 + (e0 >> 1) + ep;
        g_woH[gi] = pk(he, ho); g_woL[gi] = pk(e - he, o - ho);
    }
}

// ------------- 128x64 GEMM body: 4 warps, 2-stage cp.async, 2 CTAs/SM -------------
// Stage (u32): AH[0,4608) AL[4608,9216) BH[9216,11520) BL[11520,13824)
// pitch 36 u32/row. Stage bytes 55296; 2 stages = 110592 B/CTA -> 2 CTAs/SM.
#define STG_B 55296
#define S_AH 0
#define S_AL 4608
#define S_BH 9216
#define S_BL 11520

__device__ __forceinline__ void gemm_issue(const u32* aH, const u32* aL,
                                           const u32* bH, const u32* bL,
                                           u32 smb, int kb) {
    int t = threadIdx.x;
    int kp0 = kb * 32;
    u32 sbase = smb + (kb & 1) * STG_B;
    for (int i = t; i < 1024; i += 128) {
        int row = i >> 3, q = (i & 7) * 4;
        u32 off = (row * 36 + q) * 4;
        size_t so = (size_t)row * 512 + kp0 + q;
        cpa16(sbase + S_AH * 4 + off, &aH[so]);
        cpa16(sbase + S_AL * 4 + off, &aL[so]);
    }
    for (int i = t; i < 512; i += 128) {
        int row = i >> 3, q = (i & 7) * 4;
        u32 off = (row * 36 + q) * 4;
        size_t so = (size_t)row * 512 + kp0 + q;
        cpa16(sbase + S_BH * 4 + off, &bH[so]);
        cpa16(sbase + S_BL * 4 + off, &bL[so]);
    }
    asm volatile("cp.async.commit_group;" ::: "memory");
}

__device__ __forceinline__ void gemm_body(const u32* aH, const u32* aL,
                                          const u32* bH, const u32* bL) {
    int t = threadIdx.x, w = t >> 5, lane = t & 31;
    u32 smb = smem_u32(dynsm);
    int m0w = (w >> 1) * 64, n0w = (w & 1) * 32;

    int rowA = (lane & 7) + ((lane >> 3) & 1) * 8;
    int colA = ((lane >> 4) & 1) * 16;
    int rowB = (lane & 7) + ((lane >> 4) & 1) * 8;
    int colB = ((lane >> 3) & 1) * 16;

    float acc[4][4][4];
    #pragma unroll
    for (int mf = 0; mf < 4; mf++)
        #pragma unroll
        for (int nf = 0; nf < 4; nf++)
            #pragma unroll
            for (int c = 0; c < 4; c++) acc[mf][nf][c] = 0.f;

    gemm_issue(aH, aL, bH, bL, smb, 0);
    for (int kb = 0; kb < 16; kb++) {
        __syncthreads();
        if (kb < 15) {
            gemm_issue(aH, aL, bH, bL, smb, kb + 1);
            asm volatile("cp.async.wait_group 1;" ::: "memory");
        } else {
            asm volatile("cp.async.wait_group 0;" ::: "memory");
        }
        __syncthreads();

        u32 sb = smb + (kb & 1) * STG_B;
        #pragma unroll
        for (int kk = 0; kk < 4; kk++) {
            u32 aHf[4][4], aLf[4][4];
            #pragma unroll
            for (int mf = 0; mf < 4; mf++) {
                u32 adr = sb + S_AH * 4 + (u32)(m0w + mf * 16 + rowA) * 144 + kk * 32 + colA;
                ldsm4(aHf[mf][0], aHf[mf][1], aHf[mf][2], aHf[mf][3], adr);
                ldsm4(aLf[mf][0], aLf[mf][1], aLf[mf][2], aLf[mf][3], adr + (S_AL - S_AH) * 4);
            }
            u32 bHf[4][2], bLf[4][2];
            #pragma unroll
            for (int nfp = 0; nfp < 2; nfp++) {
                u32 adr = sb + S_BH * 4 + (u32)(n0w + nfp * 16 + rowB) * 144 + kk * 32 + colB;
                ldsm4(bHf[2*nfp][0], bHf[2*nfp][1], bHf[2*nfp+1][0], bHf[2*nfp+1][1], adr);
                ldsm4(bLf[2*nfp][0], bLf[2*nfp][1], bLf[2*nfp+1][0], bLf[2*nfp+1][1],
                      adr + (S_BL - S_BH) * 4);
            }
            #pragma unroll
            for (int nf = 0; nf < 4; nf++)
                #pragma unroll
                for (int mf = 0; mf < 4; mf++) {
                    mma16816(acc[mf][nf], aHf[mf], bHf[nf][0], bHf[nf][1]);
                    mma16816(acc[mf][nf], aLf[mf], bHf[nf][0], bHf[nf][1]);
                    mma16816(acc[mf][nf], aHf[mf], bLf[nf][0], bLf[nf][1]);
                }
        }
    }

    // stage accumulators to Cs [128][69]
    __syncthreads();
    float* Cs = (float*)dynsm; const int CP = 69;
    int g = lane >> 2, r = lane & 3;
    #pragma unroll
    for (int mf = 0; mf < 4; mf++)
        #pragma unroll
        for (int nf = 0; nf < 4; nf++) {
            int row = m0w + mf * 16 + g, col = n0w + nf * 8 + 2 * r;
            Cs[row * CP + col] = acc[mf][nf][0];
            Cs[row * CP + col + 1] = acc[mf][nf][1];
            Cs[(row + 8) * CP + col] = acc[mf][nf][2];
            Cs[(row + 8) * CP + col + 1] = acc[mf][nf][3];
        }
    __syncthreads();
}

// ---------------- fused QKV GEMM: grid (32, 48), 128 threads ----------------
// y: mat = y/16, head = y%16. Tile: 128 l-rows x 64 dk-cols (one head).
__global__ __launch_bounds__(128) void qkv_gemm() {
    int brow = blockIdx.x * 128;
    int b = brow >> 11, lloc = brow & 2047;
    int mat = blockIdx.y >> 4, h = blockIdx.y & 15;
    int t = threadIdx.x;

    const size_t wbase = (size_t)(mat * Hh + h) * DKk * 512;
    gemm_body(g_xH + (size_t)brow * 512, g_xL + (size_t)brow * 512,
              g_wH + wbase, g_wL + wbase);

    float* Cs = (float*)dynsm; const int CP = 69;
    if (mat < 2) {
        u32* dH = mat ? g_KH : g_QH;
        u32* dL = mat ? g_KL : g_QL;
        for (int i = t; i < 128 * 32; i += 128) {
            int lr = i >> 5, dkp = i & 31;
            float v0 = Cs[lr * CP + 2 * dkp], v1 = Cs[lr * CP + 2 * dkp + 1];
            float h1 = bhi(v0), h2 = bhi(v1);
            size_t gi = ((size_t)(b * 16 + h) * Ll + lloc + lr) * 32 + dkp;
            dH[gi] = pk(h1, h2); dL[gi] = pk(v0 - h1, v1 - h2);
        }
    } else {
        for (int i = t; i < 64 * 64; i += 128) {
            int dk = i >> 6, lp = i & 63;
            float v0 = Cs[(2 * lp) * CP + dk], v1 = Cs[(2 * lp + 1) * CP + dk];
            float h1 = bhi(v0), h2 = bhi(v1);
            size_t gi = ((size_t)(b * 16 + h) * DKk + dk) * 1024 + (lloc >> 1) + lp;
            g_VtH[gi] = pk(h1, h2); g_VtL[gi] = pk(v0 - h1, v1 - h2);
        }
    }
}

// ---------------- output projection: grid (32, 16), 128 threads ----------------
__global__ __launch_bounds__(128) void oproj_gemm(float* __restrict__ out) {
    int brow = blockIdx.x * 128;
    int b = brow >> 11, lloc = brow & 2047;
    int d0 = blockIdx.y * 64;
    int t = threadIdx.x;

    gemm_body(g_HdH + (size_t)brow * 512, g_HdL + (size_t)brow * 512,
              g_woH + (size_t)d0 * 512, g_woL + (size_t)d0 * 512);

    float* Cs = (float*)dynsm; const int CP = 69;
    for (int i = t; i < 128 * 64; i += 128) {
        int dc = i >> 7, lc = i & 127;
        out[((size_t)b * Dd + d0 + dc) * Ll + lloc + lc] = Cs[lc * CP + dc];
    }
}

// ---------------- flash attention: warp-private softmax + cp.async ----------------
// 8 warps x 16 rows each; all 64 keys per warp. 2 CTAs/SM via launch_bounds.
#define FST0 9216
#define FSSTR 9344
#define FLASH_U32 (9216 + 2 * 9344)

__device__ __forceinline__ void flash_issue(const u32* kH, const u32* kL,
                                            const u32* vH, const u32* vL,
                                            const float* mrow_g, u32 smb, int kb) {
    int t = threadIdx.x;
    u32 sb = smb + (FST0 + (kb & 1) * FSSTR) * 4;
    int kp0 = kb * 32;
    for (int c = t; c < 512; c += 256) {
        int row = c >> 3, q = (c & 7) * 4;
        u32 d = sb + (row * 36 + q) * 4;
        cpa16(d,            &kH[(size_t)(kb * 64 + row) * 32 + q]);
        cpa16(d + 2304 * 4, &kL[(size_t)(kb * 64 + row) * 32 + q]);
        cpa16(d + 4608 * 4, &vH[(size_t)row * 1024 + kp0 + q]);
        cpa16(d + 6912 * 4, &vL[(size_t)row * 1024 + kp0 + q]);
    }
    if (t < 16) cpa16(sb + 9216 * 4 + t * 16, &mrow_g[kb * 64 + t * 4]);
    asm volatile("cp.async.commit_group;" ::: "memory");
}

__global__ __launch_bounds__(256, 2) void flash_mma(const float* __restrict__ mask) {
    int bh = blockIdx.y, b = bh >> 4, h = bh & 15, l0 = blockIdx.x * 128;
    int t = threadIdx.x, w = t >> 5, lane = t & 31, g = lane >> 2, r = lane & 3;
    int m0w = w * 16;
    u32 smb = smem_u32(dynsm);

    int rowA = (lane & 7) + ((lane >> 3) & 1) * 8;
    int colA = ((lane >> 4) & 1) * 16;
    int rowB = (lane & 7) + ((lane >> 4) & 1) * 8;
    int colB = ((lane >> 3) & 1) * 16;

    const u32* kHp = g_KH + (size_t)bh * Ll * 32;
    const u32* kLp = g_KL + (size_t)bh * Ll * 32;
    const u32* vHp = g_VtH + (size_t)bh * DKk * 1024;
    const u32* vLp = g_VtL + (size_t)bh * DKk * 1024;
    const float* mg = mask + (size_t)b * Ll;

    flash_issue(kHp, kLp, vHp, vLp, mg, smb, 0);

    const u32* qH = g_QH + ((size_t)bh * Ll + l0) * 32;
    const u32* qL = g_QL + ((size_t)bh * Ll + l0) * 32;
    for (int i = t; i < 1024; i += 256) {
        int row = i >> 3, q = (i & 7) * 4;
        *(uint4*)&dynsm[row * 36 + q]        = *(const uint4*)&qH[(size_t)row * 32 + q];
        *(uint4*)&dynsm[4608 + row * 36 + q] = *(const uint4*)&qL[(size_t)row * 32 + q];
    }

    float O[8][4];
    #pragma unroll
    for (int nf = 0; nf < 8; nf++)
        #pragma unroll
        for (int c = 0; c < 4; c++) O[nf][c] = 0.f;
    float mA = -INFINITY, mB = -INFINITY, lA = 0.f, lB = 0.f;

    for (int kb = 0; kb < 32; kb++) {
        asm volatile("cp.async.wait_group 0;" ::: "memory");
        __syncthreads();
        if (kb < 31) flash_issue(kHp, kLp, vHp, vLp, mg, smb, kb + 1);

        u32 sb = smb + (FST0 + (kb & 1) * FSSTR) * 4;
        float* kms = (float*)(dynsm + FST0 + (kb & 1) * FSSTR + 9216);

        float sa[8][4];
        #pragma unroll
        for (int nf = 0; nf < 8; nf++)
            #pragma unroll
            for (int c = 0; c < 4; c++) sa[nf][c] = 0.f;
        #pragma unroll
        for (int kk = 0; kk < 4; kk++) {
            u32 aH[4], aL[4];
            u32 adrQ = smb + (u32)(m0w + rowA) * 144 + kk * 32 + colA;
            ldsm4(aH[0], aH[1], aH[2], aH[3], adrQ);
            ldsm4(aL[0], aL[1], aL[2], aL[3], adrQ + 4608 * 4);
            u32 bH[8][2], bL[8][2];
            #pragma unroll
            for (int nfp = 0; nfp < 4; nfp++) {
                u32 adrK = sb + (u32)(nfp * 16 + rowB) * 144 + kk * 32 + colB;
                ldsm4(bH[2*nfp][0], bH[2*nfp][1], bH[2*nfp+1][0], bH[2*nfp+1][1], adrK);
                ldsm4(bL[2*nfp][0], bL[2*nfp][1], bL[2*nfp+1][0], bL[2*nfp+1][1], adrK + 2304 * 4);
            }
            #pragma unroll
            for (int nf = 0; nf < 8; nf++) {
                mma16816(sa[nf], aH, bH[nf][0], bH[nf][1]);
                mma16816(sa[nf], aL, bH[nf][0], bH[nf][1]);
                mma16816(sa[nf], aH, bL[nf][0], bL[nf][1]);
            }
        }

        float pmA = -INFINITY, pmB = -INFINITY;
        #pragma unroll
        for (int nf = 0; nf < 8; nf++) {
            int kc = nf * 8 + 2 * r;
            bool k0 = kms[kc] > 0.5f, k1 = kms[kc + 1] > 0.5f;
            if (!k0) { sa[nf][0] = -1e30f; sa[nf][2] = -1e30f; }
            if (!k1) { sa[nf][1] = -1e30f; sa[nf][3] = -1e30f; }
            pmA = fmaxf(pmA, fmaxf(sa[nf][0], sa[nf][1]));
            pmB = fmaxf(pmB, fmaxf(sa[nf][2], sa[nf][3]));
        }
        pmA = fmaxf(pmA, __shfl_xor_sync(0xffffffffu, pmA, 1));
        pmA = fmaxf(pmA, __shfl_xor_sync(0xffffffffu, pmA, 2));
        pmB = fmaxf(pmB, __shfl_xor_sync(0xffffffffu, pmB, 1));
        pmB = fmaxf(pmB, __shfl_xor_sync(0xffffffffu, pmB, 2));
        float mnA = fmaxf(mA, pmA), mnB = fmaxf(mB, pmB);
        float alA = __expf(mA - mnA), alB = __expf(mB - mnB);
        float psA = 0.f, psB = 0.f;
        #pragma unroll
        for (int nf = 0; nf < 8; nf++) {
            float e0 = __expf(sa[nf][0] - mnA), e1 = __expf(sa[nf][1] - mnA);
            float e2 = __expf(sa[nf][2] - mnB), e3 = __expf(sa[nf][3] - mnB);
            sa[nf][0] = e0; sa[nf][1] = e1; sa[nf][2] = e2; sa[nf][3] = e3;
            psA += e0 + e1; psB += e2 + e3;
        }
        psA += __shfl_xor_sync(0xffffffffu, psA, 1);
        psA += __shfl_xor_sync(0xffffffffu, psA, 2);
        psB += __shfl_xor_sync(0xffffffffu, psB, 1);
        psB += __shfl_xor_sync(0xffffffffu, psB, 2);
        lA = lA * alA + psA; lB = lB * alB + psB;
        mA = mnA; mB = mnB;
        #pragma unroll
        for (int nf = 0; nf < 8; nf++) {
            O[nf][0] *= alA; O[nf][1] *= alA;
            O[nf][2] *= alB; O[nf][3] *= alB;
        }

        #pragma unroll
        for (int kp = 0; kp < 4; kp++) {
            float e00 = sa[2*kp][0],   e01 = sa[2*kp][1],   e02 = sa[2*kp][2],   e03 = sa[2*kp][3];
            float e10 = sa[2*kp+1][0], e11 = sa[2*kp+1][1], e12 = sa[2*kp+1][2], e13 = sa[2*kp+1][3];
            float h00 = bhi(e00), h01 = bhi(e01), h02 = bhi(e02), h03 = bhi(e03);
            float h10 = bhi(e10), h11 = bhi(e11), h12 = bhi(e12), h13 = bhi(e13);
            u32 pHf[4] = { pk(h00, h01), pk(h02, h03), pk(h10, h11), pk(h12, h13) };
            u32 pLf[4] = { pk(e00 - h00, e01 - h01), pk(e02 - h02, e03 - h03),
                           pk(e10 - h10, e11 - h11), pk(e12 - h12, e13 - h13) };
            u32 bH[8][2], bL[8][2];
            #pragma unroll
            for (int nfp = 0; nfp < 4; nfp++) {
                u32 adrV = sb + 4608 * 4 + (u32)(nfp * 16 + rowB) * 144 + kp * 32 + colB;
                ldsm4(bH[2*nfp][0], bH[2*nfp][1], bH[2*nfp+1][0], bH[2*nfp+1][1], adrV);
                ldsm4(bL[2*nfp][0], bL[2*nfp][1], bL[2*nfp+1][0], bL[2*nfp+1][1], adrV + 2304 * 4);
            }
            #pragma unroll
            for (int nf = 0; nf < 8; nf++) {
                mma16816(O[nf], pHf, bH[nf][0], bH[nf][1]);
                mma16816(O[nf], pLf, bH[nf][0], bH[nf][1]);
                mma16816(O[nf], pHf, bL[nf][0], bL[nf][1]);
            }
        }
    }

    int row = m0w + g;
    float s0 = mg[l0 + row] / lA;
    float s1 = mg[l0 + row + 8] / lB;
    #pragma unroll
    for (int nf = 0; nf < 8; nf++) {
        float c0 = O[nf][0] * s0, c1 = O[nf][1] * s0;
        float c2 = O[nf][2] * s1, c3 = O[nf][3] * s1;
        size_t gi = ((size_t)b * Ll + l0 + row) * 512 + h * 32 + nf * 4 + r;
        float h0 = bhi(c0), h1 = bhi(c1);
        g_HdH[gi] = pk(h0, h1); g_HdL[gi] = pk(c0 - h0, c1 - h1);
        float h2 = bhi(c2), h3 = bhi(c3);
        g_HdH[gi + 8 * 512] = pk(h2, h3);
        g_HdL[gi + 8 * 512] = pk(c2 - h2, c3 - h3);
    }
}

// ---------------------------------------------------------------------------
extern "C" void kernel_launch(void* const* d_in, const int* in_sizes, int n_in,
                              void* d_out, int out_size) {
    const float* x    = (const float*)d_in[0];
    const float* mask = (const float*)d_in[1];
    const float* Wq   = (const float*)d_in[2];
    const float* Wk   = (const float*)d_in[3];
    const float* Wv   = (const float*)d_in[4];
    const float* Wo   = (const float*)d_in[5];
    float* out = (float*)d_out;

    const int GEMM_SMEM  = 2 * STG_B;        // 110592 B -> 2 CTAs/SM
    const int FLASH_SMEM = FLASH_U32 * 4;    // 111616 B
    cudaFuncSetAttribute(qkv_gemm,  cudaFuncAttributeMaxDynamicSharedMemorySize, GEMM_SMEM);
    cudaFuncSetAttribute(oproj_gemm, cudaFuncAttributeMaxDynamicSharedMemorySize, GEMM_SMEM);
    cudaFuncSetAttribute(flash_mma, cudaFuncAttributeMaxDynamicSharedMemorySize, FLASH_SMEM);

    x_split<<<dim3(Ll / 64, Dd / 64, Bz), 256>>>(x);
    w_split_t<<<dim3(Dd / 64, Hh, 3), 256>>>(Wq, Wk, Wv);
    wo_split_t<<<dim3(Dd / 64, Dd / 64), 256>>>(Wo);
    qkv_gemm<<<dim3(32, 48), 128, GEMM_SMEM>>>();
    flash_mma<<<dim3(Ll / 128, BH), 256, FLASH_SMEM>>>(mask);
    oproj_gemm<<<dim3(32, 16), 128, GEMM_SMEM>>>(out);
}